// round 2
// baseline (speedup 1.0000x reference)
#include <cuda_runtime.h>
#include <math.h>

#define RB    8          // batch
#define RR    32         // resolution
#define CC    128        // channels
#define HH    4          // heads
#define HDIM  32         // head dim
#define BSZ   4          // window size
#define GG    8          // windows per axis
#define NN    64         // tokens per window
#define TT    (RB*RR*RR*RR)   // 262144 tokens
#define MLPD  512

// Scratch for x after attention residual (134 MB). __device__ global = allowed scratch.
__device__ float g_x[(size_t)TT * CC];

// ---------------- smem layouts (in floats) ----------------
#define XLN_STRIDE 132
#define QKV_STRIDE 388
#define AO_STRIDE  132
#define K1_XLN  0
#define K1_QKV  (K1_XLN + 64*XLN_STRIDE)          // 8448
#define K1_AO   (K1_QKV + 64*QKV_STRIDE)          // 33280
#define K1_BIAS (K1_AO + 64*AO_STRIDE)            // 41728
#define K1_INT  (K1_BIAS + 488)                   // 42216 (int region: 64 lab + 64 row)
#define K1_FLOATS (K1_INT + 128)
#define SMEM1_BYTES (K1_FLOATS * 4)               // 169376

#define H_STRIDE 516
#define K2_XLN 0
#define K2_H   (64*XLN_STRIDE)                    // 8448
#define K2_FLOATS (K2_H + 64*H_STRIDE)            // 41472
#define SMEM2_BYTES (K2_FLOATS * 4)               // 165888

__global__ void __launch_bounds__(256)
attn_kernel(const float* __restrict__ inputs, const float* __restrict__ qkv_w,
            const float* __restrict__ proj_w, const float* __restrict__ proj_b,
            const float* __restrict__ bias_table,
            const float* __restrict__ g1, const float* __restrict__ b1)
{
    extern __shared__ float sm[];
    float* s_xln  = sm + K1_XLN;
    float* s_qkv  = sm + K1_QKV;
    float* s_ao   = sm + K1_AO;
    float* s_bias = sm + K1_BIAS;
    int*   s_lab  = (int*)(sm + K1_INT);
    int*   s_row  = s_lab + 64;

    const int tid  = threadIdx.x;
    const int blk  = blockIdx.x;
    const int b    = blk >> 9;        // / 512
    const int w    = blk & 511;
    const int G1 = w >> 6, G2 = (w >> 3) & 7, G3 = w & 7;

    // bias table -> smem (121 x 4)
    for (int i = tid; i < 484; i += 256) s_bias[i] = bias_table[i];

    const int warp = tid >> 5, lane = tid & 31;

    // ---------------- Phase A: gather + LN1 ----------------
    for (int it = 0; it < 8; ++it) {
        int n  = warp + it * 8;
        int t1 = n >> 4, t2 = (n >> 2) & 3, t3 = n & 3;
        int s1 = G1 * 4 + t1, s2 = G2 * 4 + t2, s3 = G3 * 4 + t3;   // shifted coords
        int i1 = (s1 + 2) & 31, i2 = (s2 + 2) & 31, i3 = (s3 + 2) & 31;
        int grow = b * 32768 + i1 * 1024 + i2 * 32 + i3;

        float4 v = ((const float4*)(inputs + (size_t)grow * CC))[lane];
        float s  = v.x + v.y + v.z + v.w;
        float ss = v.x*v.x + v.y*v.y + v.z*v.z + v.w*v.w;
        #pragma unroll
        for (int o = 16; o; o >>= 1) {
            s  += __shfl_xor_sync(0xffffffffu, s,  o);
            ss += __shfl_xor_sync(0xffffffffu, ss, o);
        }
        float mean = s * (1.0f / 128.0f);
        float var  = ss * (1.0f / 128.0f) - mean * mean;
        float inv  = rsqrtf(var + 1e-5f);
        float4 gg = ((const float4*)g1)[lane];
        float4 bb = ((const float4*)b1)[lane];
        float4 o;
        o.x = (v.x - mean) * inv * gg.x + bb.x;
        o.y = (v.y - mean) * inv * gg.y + bb.y;
        o.z = (v.z - mean) * inv * gg.z + bb.z;
        o.w = (v.w - mean) * inv * gg.w + bb.w;
        ((float4*)(s_xln + n * XLN_STRIDE))[lane] = o;

        if (lane == 0) {
            s_row[n] = grow;
            int r1 = s1 < 28 ? 0 : (s1 < 30 ? 1 : 2);
            int r2 = s2 < 28 ? 0 : (s2 < 30 ? 1 : 2);
            int r3 = s3 < 28 ? 0 : (s3 < 30 ? 1 : 2);
            s_lab[n] = r1 * 9 + r2 * 3 + r3;
        }
    }
    __syncthreads();

    // ---------------- Phase B: QKV GEMM (64x384, K=128) ----------------
    const int rt = tid >> 4, ct = tid & 15;
    const int r0 = rt * 4, c0 = ct * 8;

    for (int sidx = 0; sidx < 3; ++sidx) {
        float acc[4][8];
        #pragma unroll
        for (int i = 0; i < 4; ++i)
            #pragma unroll
            for (int j = 0; j < 8; ++j) acc[i][j] = 0.0f;

        const float* wp = qkv_w + sidx * 128 + c0;
        #pragma unroll 8
        for (int k = 0; k < 128; ++k) {
            float4 b0 = __ldg((const float4*)(wp + (size_t)k * 384));
            float4 b1v = __ldg((const float4*)(wp + (size_t)k * 384 + 4));
            float a0 = s_xln[(r0 + 0) * XLN_STRIDE + k];
            float a1 = s_xln[(r0 + 1) * XLN_STRIDE + k];
            float a2 = s_xln[(r0 + 2) * XLN_STRIDE + k];
            float a3 = s_xln[(r0 + 3) * XLN_STRIDE + k];
            float bv[8] = {b0.x, b0.y, b0.z, b0.w, b1v.x, b1v.y, b1v.z, b1v.w};
            #pragma unroll
            for (int j = 0; j < 8; ++j) {
                acc[0][j] += a0 * bv[j];
                acc[1][j] += a1 * bv[j];
                acc[2][j] += a2 * bv[j];
                acc[3][j] += a3 * bv[j];
            }
        }
        float scale = (sidx == 0) ? 0.17677669529663687f : 1.0f;
        #pragma unroll
        for (int i = 0; i < 4; ++i)
            #pragma unroll
            for (int j = 0; j < 8; ++j)
                s_qkv[(r0 + i) * QKV_STRIDE + sidx * 128 + c0 + j] = acc[i][j] * scale;
    }
    __syncthreads();

    // ---------------- Phase C: attention, one (head,row) per thread ----------------
    {
        const int h  = tid >> 6;
        const int nq = tid & 63;
        const int t1n = nq >> 4, t2n = (nq >> 2) & 3, t3n = nq & 3;
        const int labn   = s_lab[nq];
        const int base_n = (t1n + 3) * 11 + (t2n + 3) + (t3n + 3);
        const float* bp  = s_bias + base_n * 4 + h;

        float4 q[8];
        const float4* qp = (const float4*)(s_qkv + nq * QKV_STRIDE + h * HDIM);
        #pragma unroll
        for (int i = 0; i < 8; ++i) q[i] = qp[i];

        float sc[64];
        float mx = -1e30f;
        #pragma unroll
        for (int m = 0; m < 64; ++m) {
            const float4* kp = (const float4*)(s_qkv + m * QKV_STRIDE + 128 + h * HDIM);
            float d = 0.0f;
            #pragma unroll
            for (int i = 0; i < 8; ++i) {
                float4 kv = kp[i];
                d += q[i].x * kv.x + q[i].y * kv.y + q[i].z * kv.z + q[i].w * kv.w;
            }
            const int off_m = 11 * (m >> 4) + ((m >> 2) & 3) + (m & 3);
            float msk = (labn == s_lab[m]) ? 0.0f : -100.0f;
            d += bp[-(off_m * 4)] + msk;
            sc[m] = d;
            mx = fmaxf(mx, d);
        }
        float sum = 0.0f;
        #pragma unroll
        for (int m = 0; m < 64; ++m) {
            float e = __expf(sc[m] - mx);
            sc[m] = e;
            sum += e;
        }
        const float invs = 1.0f / sum;

        float4 acc[8];
        #pragma unroll
        for (int i = 0; i < 8; ++i) acc[i] = make_float4(0.f, 0.f, 0.f, 0.f);
        #pragma unroll
        for (int m = 0; m < 64; ++m) {
            const float p = sc[m] * invs;
            const float4* vp = (const float4*)(s_qkv + m * QKV_STRIDE + 256 + h * HDIM);
            #pragma unroll
            for (int i = 0; i < 8; ++i) {
                float4 vv = vp[i];
                acc[i].x += p * vv.x; acc[i].y += p * vv.y;
                acc[i].z += p * vv.z; acc[i].w += p * vv.w;
            }
        }
        float4* op = (float4*)(s_ao + nq * AO_STRIDE + h * HDIM);
        #pragma unroll
        for (int i = 0; i < 8; ++i) op[i] = acc[i];
    }
    __syncthreads();

    // ---------------- Phase D: proj GEMM + residual scatter ----------------
    {
        float acc[4][8];
        #pragma unroll
        for (int i = 0; i < 4; ++i)
            #pragma unroll
            for (int j = 0; j < 8; ++j) acc[i][j] = 0.0f;

        const float* wp = proj_w + c0;
        #pragma unroll 8
        for (int k = 0; k < 128; ++k) {
            float4 b0 = __ldg((const float4*)(wp + (size_t)k * 128));
            float4 b1v = __ldg((const float4*)(wp + (size_t)k * 128 + 4));
            float a0 = s_ao[(r0 + 0) * AO_STRIDE + k];
            float a1 = s_ao[(r0 + 1) * AO_STRIDE + k];
            float a2 = s_ao[(r0 + 2) * AO_STRIDE + k];
            float a3 = s_ao[(r0 + 3) * AO_STRIDE + k];
            float bv[8] = {b0.x, b0.y, b0.z, b0.w, b1v.x, b1v.y, b1v.z, b1v.w};
            #pragma unroll
            for (int j = 0; j < 8; ++j) {
                acc[0][j] += a0 * bv[j];
                acc[1][j] += a1 * bv[j];
                acc[2][j] += a2 * bv[j];
                acc[3][j] += a3 * bv[j];
            }
        }
        float4 pb0 = __ldg((const float4*)(proj_b + c0));
        float4 pb1 = __ldg((const float4*)(proj_b + c0 + 4));
        #pragma unroll
        for (int i = 0; i < 4; ++i) {
            int grow = s_row[r0 + i];
            const float* ip = inputs + (size_t)grow * CC + c0;
            float4 x0 = ((const float4*)ip)[0];
            float4 x1 = ((const float4*)ip)[1];
            float4 o0, o1;
            o0.x = (acc[i][0] + pb0.x) * 0.5f + x0.x;
            o0.y = (acc[i][1] + pb0.y) * 0.5f + x0.y;
            o0.z = (acc[i][2] + pb0.z) * 0.5f + x0.z;
            o0.w = (acc[i][3] + pb0.w) * 0.5f + x0.w;
            o1.x = (acc[i][4] + pb1.x) * 0.5f + x1.x;
            o1.y = (acc[i][5] + pb1.y) * 0.5f + x1.y;
            o1.z = (acc[i][6] + pb1.z) * 0.5f + x1.z;
            o1.w = (acc[i][7] + pb1.w) * 0.5f + x1.w;
            float* xp = g_x + (size_t)grow * CC + c0;
            ((float4*)xp)[0] = o0;
            ((float4*)xp)[1] = o1;
        }
    }
}

__global__ void __launch_bounds__(256)
mlp_kernel(const float* __restrict__ g2, const float* __restrict__ b2,
           const float* __restrict__ w1, const float* __restrict__ bb1,
           const float* __restrict__ w2, const float* __restrict__ bb2,
           float* __restrict__ out)
{
    extern __shared__ float sm[];
    float* s_xln = sm + K2_XLN;
    float* s_h   = sm + K2_H;

    const int tid  = threadIdx.x;
    const int warp = tid >> 5, lane = tid & 31;
    const size_t row0 = (size_t)blockIdx.x * 64;

    // LN2
    for (int it = 0; it < 8; ++it) {
        int rloc = warp + it * 8;
        float4 v = ((const float4*)(g_x + (row0 + rloc) * CC))[lane];
        float s  = v.x + v.y + v.z + v.w;
        float ss = v.x*v.x + v.y*v.y + v.z*v.z + v.w*v.w;
        #pragma unroll
        for (int o = 16; o; o >>= 1) {
            s  += __shfl_xor_sync(0xffffffffu, s,  o);
            ss += __shfl_xor_sync(0xffffffffu, ss, o);
        }
        float mean = s * (1.0f / 128.0f);
        float var  = ss * (1.0f / 128.0f) - mean * mean;
        float inv  = rsqrtf(var + 1e-5f);
        float4 gg = ((const float4*)g2)[lane];
        float4 bb = ((const float4*)b2)[lane];
        float4 o;
        o.x = (v.x - mean) * inv * gg.x + bb.x;
        o.y = (v.y - mean) * inv * gg.y + bb.y;
        o.z = (v.z - mean) * inv * gg.z + bb.z;
        o.w = (v.w - mean) * inv * gg.w + bb.w;
        ((float4*)(s_xln + rloc * XLN_STRIDE))[lane] = o;
    }
    __syncthreads();

    const int rt = tid >> 4, ct = tid & 15;
    const int r0 = rt * 4, c0 = ct * 8;

    // GEMM1 (128 -> 512) + GELU(exact erf)
    for (int pass = 0; pass < 4; ++pass) {
        float acc[4][8];
        #pragma unroll
        for (int i = 0; i < 4; ++i)
            #pragma unroll
            for (int j = 0; j < 8; ++j) acc[i][j] = 0.0f;

        const float* wp = w1 + pass * 128 + c0;
        #pragma unroll 8
        for (int k = 0; k < 128; ++k) {
            float4 b0 = __ldg((const float4*)(wp + (size_t)k * 512));
            float4 b1v = __ldg((const float4*)(wp + (size_t)k * 512 + 4));
            float a0 = s_xln[(r0 + 0) * XLN_STRIDE + k];
            float a1 = s_xln[(r0 + 1) * XLN_STRIDE + k];
            float a2 = s_xln[(r0 + 2) * XLN_STRIDE + k];
            float a3 = s_xln[(r0 + 3) * XLN_STRIDE + k];
            float bv[8] = {b0.x, b0.y, b0.z, b0.w, b1v.x, b1v.y, b1v.z, b1v.w};
            #pragma unroll
            for (int j = 0; j < 8; ++j) {
                acc[0][j] += a0 * bv[j];
                acc[1][j] += a1 * bv[j];
                acc[2][j] += a2 * bv[j];
                acc[3][j] += a3 * bv[j];
            }
        }
        float4 q0 = __ldg((const float4*)(bb1 + pass * 128 + c0));
        float4 q1 = __ldg((const float4*)(bb1 + pass * 128 + c0 + 4));
        float bias[8] = {q0.x, q0.y, q0.z, q0.w, q1.x, q1.y, q1.z, q1.w};
        #pragma unroll
        for (int i = 0; i < 4; ++i)
            #pragma unroll
            for (int j = 0; j < 8; ++j) {
                float v = acc[i][j] + bias[j];
                v = 0.5f * v * (1.0f + erff(v * 0.70710678118654752f));
                s_h[(r0 + i) * H_STRIDE + pass * 128 + c0 + j] = v;
            }
    }
    __syncthreads();

    // GEMM2 (512 -> 128) + final residual
    {
        float acc[4][8];
        #pragma unroll
        for (int i = 0; i < 4; ++i)
            #pragma unroll
            for (int j = 0; j < 8; ++j) acc[i][j] = 0.0f;

        const float* wp = w2 + c0;
        #pragma unroll 8
        for (int k = 0; k < 512; ++k) {
            float4 b0 = __ldg((const float4*)(wp + (size_t)k * 128));
            float4 b1v = __ldg((const float4*)(wp + (size_t)k * 128 + 4));
            float a0 = s_h[(r0 + 0) * H_STRIDE + k];
            float a1 = s_h[(r0 + 1) * H_STRIDE + k];
            float a2 = s_h[(r0 + 2) * H_STRIDE + k];
            float a3 = s_h[(r0 + 3) * H_STRIDE + k];
            float bv[8] = {b0.x, b0.y, b0.z, b0.w, b1v.x, b1v.y, b1v.z, b1v.w};
            #pragma unroll
            for (int j = 0; j < 8; ++j) {
                acc[0][j] += a0 * bv[j];
                acc[1][j] += a1 * bv[j];
                acc[2][j] += a2 * bv[j];
                acc[3][j] += a3 * bv[j];
            }
        }
        float4 q0 = __ldg((const float4*)(bb2 + c0));
        float4 q1 = __ldg((const float4*)(bb2 + c0 + 4));
        #pragma unroll
        for (int i = 0; i < 4; ++i) {
            const float* xp = g_x + (row0 + r0 + i) * CC + c0;
            float4 x0 = ((const float4*)xp)[0];
            float4 x1 = ((const float4*)xp)[1];
            float4 o0, o1;
            o0.x = (acc[i][0] + q0.x) * 0.5f + x0.x;
            o0.y = (acc[i][1] + q0.y) * 0.5f + x0.y;
            o0.z = (acc[i][2] + q0.z) * 0.5f + x0.z;
            o0.w = (acc[i][3] + q0.w) * 0.5f + x0.w;
            o1.x = (acc[i][4] + q1.x) * 0.5f + x1.x;
            o1.y = (acc[i][5] + q1.y) * 0.5f + x1.y;
            o1.z = (acc[i][6] + q1.z) * 0.5f + x1.z;
            o1.w = (acc[i][7] + q1.w) * 0.5f + x1.w;
            float* op = out + (row0 + r0 + i) * CC + c0;
            ((float4*)op)[0] = o0;
            ((float4*)op)[1] = o1;
        }
    }
}

extern "C" void kernel_launch(void* const* d_in, const int* in_sizes, int n_in,
                              void* d_out, int out_size)
{
    const float* inputs     = (const float*)d_in[0];
    const float* qkv_w      = (const float*)d_in[1];
    const float* proj_w     = (const float*)d_in[2];
    const float* proj_b     = (const float*)d_in[3];
    const float* bias_table = (const float*)d_in[4];
    const float* g1         = (const float*)d_in[5];
    const float* b1         = (const float*)d_in[6];
    const float* g2         = (const float*)d_in[7];
    const float* b2         = (const float*)d_in[8];
    const float* w1         = (const float*)d_in[9];
    const float* bb1        = (const float*)d_in[10];
    const float* w2         = (const float*)d_in[11];
    const float* bb2        = (const float*)d_in[12];
    float* out = (float*)d_out;

    cudaFuncSetAttribute(attn_kernel, cudaFuncAttributeMaxDynamicSharedMemorySize, SMEM1_BYTES);
    cudaFuncSetAttribute(mlp_kernel,  cudaFuncAttributeMaxDynamicSharedMemorySize, SMEM2_BYTES);

    attn_kernel<<<RB * 512, 256, SMEM1_BYTES>>>(inputs, qkv_w, proj_w, proj_b,
                                                bias_table, g1, b1);
    mlp_kernel<<<TT / 64, 256, SMEM2_BYTES>>>(g2, b2, w1, bb1, w2, bb2, out);
}

// round 4
// speedup vs baseline: 2.3496x; 2.3496x over previous
#include <cuda_runtime.h>
#include <cuda_bf16.h>
#include <math.h>
#include <stdint.h>

#define RB    8
#define RR    32
#define CC    128
#define HH    4
#define HDIM  32
#define NN    64
#define TT    (RB*RR*RR*RR)   // 262144 tokens
#define MLPD  512

// ---------------- device scratch ----------------
__device__ float g_x[(size_t)TT * CC];                   // x after attn residual
__device__ __nv_bfloat16 g_w1[CC * MLPD];                // w1 bf16 [128 K][512 N] row-major
__device__ __nv_bfloat16 g_w2[MLPD * CC];                // w2 bf16 [512 K][128 N] row-major

__device__ __forceinline__ uint32_t smem_u32(const void* p) {
    uint32_t a;
    asm("{ .reg .u64 t; cvta.to.shared.u64 t, %1; cvt.u32.u64 %0, t; }" : "=r"(a) : "l"(p));
    return a;
}

// ---------------- MLP HMMA smem layout (bytes) ----------------
// A: 128 x 136 bf16   = 34816
// B: 128 x 136 bf16   = 34816
// H: 128 x 520 bf16   = 133120
#define SA_OFF 0
#define SB_OFF 34816
#define SH_OFF 69632
#define SMEM_MLP (SH_OFF + 133120)        // 202752
#define SA_STRIDE_B 272                   // bytes per row
#define SB_STRIDE_B 272
#define SH_STRIDE_B 1040

// ---------------- attention kernel smem (floats) ----------------
#define XLN_STRIDE 132
#define QKV_STRIDE 388
#define AO_STRIDE  132
#define K1_XLN  0
#define K1_QKV  (K1_XLN + 64*XLN_STRIDE)
#define K1_AO   (K1_QKV + 64*QKV_STRIDE)
#define K1_BIAS (K1_AO + 64*AO_STRIDE)
#define K1_INT  (K1_BIAS + 488)
#define K1_FLOATS (K1_INT + 128)
#define SMEM1_BYTES (K1_FLOATS * 4)

// ================= prep: fp32 -> bf16 weights (no transpose needed) ======
__global__ void __launch_bounds__(256)
prep_kernel(const float* __restrict__ w1, const float* __restrict__ w2)
{
    int idx = blockIdx.x * 256 + threadIdx.x;
    if (idx < CC * MLPD) {
        g_w1[idx] = __float2bfloat16(w1[idx]);
    } else {
        int j = idx - CC * MLPD;
        g_w2[j] = __float2bfloat16(w2[j]);
    }
}

// ================= attention kernel (unchanged from R2 pass) =================
__global__ void __launch_bounds__(256)
attn_kernel(const float* __restrict__ inputs, const float* __restrict__ qkv_w,
            const float* __restrict__ proj_w, const float* __restrict__ proj_b,
            const float* __restrict__ bias_table,
            const float* __restrict__ g1, const float* __restrict__ b1)
{
    extern __shared__ float sm[];
    float* s_xln  = sm + K1_XLN;
    float* s_qkv  = sm + K1_QKV;
    float* s_ao   = sm + K1_AO;
    float* s_bias = sm + K1_BIAS;
    int*   s_lab  = (int*)(sm + K1_INT);
    int*   s_row  = s_lab + 64;

    const int tid  = threadIdx.x;
    const int blk  = blockIdx.x;
    const int b    = blk >> 9;
    const int w    = blk & 511;
    const int G1 = w >> 6, G2 = (w >> 3) & 7, G3 = w & 7;

    for (int i = tid; i < 484; i += 256) s_bias[i] = bias_table[i];

    const int warp = tid >> 5, lane = tid & 31;

    for (int it = 0; it < 8; ++it) {
        int n  = warp + it * 8;
        int t1 = n >> 4, t2 = (n >> 2) & 3, t3 = n & 3;
        int s1 = G1 * 4 + t1, s2 = G2 * 4 + t2, s3 = G3 * 4 + t3;
        int i1 = (s1 + 2) & 31, i2 = (s2 + 2) & 31, i3 = (s3 + 2) & 31;
        int grow = b * 32768 + i1 * 1024 + i2 * 32 + i3;

        float4 v = ((const float4*)(inputs + (size_t)grow * CC))[lane];
        float s  = v.x + v.y + v.z + v.w;
        float ss = v.x*v.x + v.y*v.y + v.z*v.z + v.w*v.w;
        #pragma unroll
        for (int o = 16; o; o >>= 1) {
            s  += __shfl_xor_sync(0xffffffffu, s,  o);
            ss += __shfl_xor_sync(0xffffffffu, ss, o);
        }
        float mean = s * (1.0f / 128.0f);
        float var  = ss * (1.0f / 128.0f) - mean * mean;
        float inv  = rsqrtf(var + 1e-5f);
        float4 gg = ((const float4*)g1)[lane];
        float4 bb = ((const float4*)b1)[lane];
        float4 o;
        o.x = (v.x - mean) * inv * gg.x + bb.x;
        o.y = (v.y - mean) * inv * gg.y + bb.y;
        o.z = (v.z - mean) * inv * gg.z + bb.z;
        o.w = (v.w - mean) * inv * gg.w + bb.w;
        ((float4*)(s_xln + n * XLN_STRIDE))[lane] = o;

        if (lane == 0) {
            s_row[n] = grow;
            int r1 = s1 < 28 ? 0 : (s1 < 30 ? 1 : 2);
            int r2 = s2 < 28 ? 0 : (s2 < 30 ? 1 : 2);
            int r3 = s3 < 28 ? 0 : (s3 < 30 ? 1 : 2);
            s_lab[n] = r1 * 9 + r2 * 3 + r3;
        }
    }
    __syncthreads();

    const int rt = tid >> 4, ct = tid & 15;
    const int r0 = rt * 4, c0 = ct * 8;

    for (int sidx = 0; sidx < 3; ++sidx) {
        float acc[4][8];
        #pragma unroll
        for (int i = 0; i < 4; ++i)
            #pragma unroll
            for (int j = 0; j < 8; ++j) acc[i][j] = 0.0f;

        const float* wp = qkv_w + sidx * 128 + c0;
        #pragma unroll 8
        for (int k = 0; k < 128; ++k) {
            float4 b0 = __ldg((const float4*)(wp + (size_t)k * 384));
            float4 b1v = __ldg((const float4*)(wp + (size_t)k * 384 + 4));
            float a0 = s_xln[(r0 + 0) * XLN_STRIDE + k];
            float a1 = s_xln[(r0 + 1) * XLN_STRIDE + k];
            float a2 = s_xln[(r0 + 2) * XLN_STRIDE + k];
            float a3 = s_xln[(r0 + 3) * XLN_STRIDE + k];
            float bv[8] = {b0.x, b0.y, b0.z, b0.w, b1v.x, b1v.y, b1v.z, b1v.w};
            #pragma unroll
            for (int j = 0; j < 8; ++j) {
                acc[0][j] += a0 * bv[j];
                acc[1][j] += a1 * bv[j];
                acc[2][j] += a2 * bv[j];
                acc[3][j] += a3 * bv[j];
            }
        }
        float scale = (sidx == 0) ? 0.17677669529663687f : 1.0f;
        #pragma unroll
        for (int i = 0; i < 4; ++i)
            #pragma unroll
            for (int j = 0; j < 8; ++j)
                s_qkv[(r0 + i) * QKV_STRIDE + sidx * 128 + c0 + j] = acc[i][j] * scale;
    }
    __syncthreads();

    {
        const int h  = tid >> 6;
        const int nq = tid & 63;
        const int t1n = nq >> 4, t2n = (nq >> 2) & 3, t3n = nq & 3;
        const int labn   = s_lab[nq];
        const int base_n = (t1n + 3) * 11 + (t2n + 3) + (t3n + 3);
        const float* bp  = s_bias + base_n * 4 + h;

        float4 q[8];
        const float4* qp = (const float4*)(s_qkv + nq * QKV_STRIDE + h * HDIM);
        #pragma unroll
        for (int i = 0; i < 8; ++i) q[i] = qp[i];

        float sc[64];
        float mx = -1e30f;
        #pragma unroll
        for (int m = 0; m < 64; ++m) {
            const float4* kp = (const float4*)(s_qkv + m * QKV_STRIDE + 128 + h * HDIM);
            float d = 0.0f;
            #pragma unroll
            for (int i = 0; i < 8; ++i) {
                float4 kv = kp[i];
                d += q[i].x * kv.x + q[i].y * kv.y + q[i].z * kv.z + q[i].w * kv.w;
            }
            const int off_m = 11 * (m >> 4) + ((m >> 2) & 3) + (m & 3);
            float msk = (labn == s_lab[m]) ? 0.0f : -100.0f;
            d += bp[-(off_m * 4)] + msk;
            sc[m] = d;
            mx = fmaxf(mx, d);
        }
        float sum = 0.0f;
        #pragma unroll
        for (int m = 0; m < 64; ++m) {
            float e = __expf(sc[m] - mx);
            sc[m] = e;
            sum += e;
        }
        const float invs = 1.0f / sum;

        float4 acc[8];
        #pragma unroll
        for (int i = 0; i < 8; ++i) acc[i] = make_float4(0.f, 0.f, 0.f, 0.f);
        #pragma unroll
        for (int m = 0; m < 64; ++m) {
            const float p = sc[m] * invs;
            const float4* vp = (const float4*)(s_qkv + m * QKV_STRIDE + 256 + h * HDIM);
            #pragma unroll
            for (int i = 0; i < 8; ++i) {
                float4 vv = vp[i];
                acc[i].x += p * vv.x; acc[i].y += p * vv.y;
                acc[i].z += p * vv.z; acc[i].w += p * vv.w;
            }
        }
        float4* op = (float4*)(s_ao + nq * AO_STRIDE + h * HDIM);
        #pragma unroll
        for (int i = 0; i < 8; ++i) op[i] = acc[i];
    }
    __syncthreads();

    {
        float acc[4][8];
        #pragma unroll
        for (int i = 0; i < 4; ++i)
            #pragma unroll
            for (int j = 0; j < 8; ++j) acc[i][j] = 0.0f;

        const float* wp = proj_w + c0;
        #pragma unroll 8
        for (int k = 0; k < 128; ++k) {
            float4 b0 = __ldg((const float4*)(wp + (size_t)k * 128));
            float4 b1v = __ldg((const float4*)(wp + (size_t)k * 128 + 4));
            float a0 = s_ao[(r0 + 0) * AO_STRIDE + k];
            float a1 = s_ao[(r0 + 1) * AO_STRIDE + k];
            float a2 = s_ao[(r0 + 2) * AO_STRIDE + k];
            float a3 = s_ao[(r0 + 3) * AO_STRIDE + k];
            float bv[8] = {b0.x, b0.y, b0.z, b0.w, b1v.x, b1v.y, b1v.z, b1v.w};
            #pragma unroll
            for (int j = 0; j < 8; ++j) {
                acc[0][j] += a0 * bv[j];
                acc[1][j] += a1 * bv[j];
                acc[2][j] += a2 * bv[j];
                acc[3][j] += a3 * bv[j];
            }
        }
        float4 pb0 = __ldg((const float4*)(proj_b + c0));
        float4 pb1 = __ldg((const float4*)(proj_b + c0 + 4));
        #pragma unroll
        for (int i = 0; i < 4; ++i) {
            int grow = s_row[r0 + i];
            const float* ip = inputs + (size_t)grow * CC + c0;
            float4 x0 = ((const float4*)ip)[0];
            float4 x1 = ((const float4*)ip)[1];
            float4 o0, o1;
            o0.x = (acc[i][0] + pb0.x) * 0.5f + x0.x;
            o0.y = (acc[i][1] + pb0.y) * 0.5f + x0.y;
            o0.z = (acc[i][2] + pb0.z) * 0.5f + x0.z;
            o0.w = (acc[i][3] + pb0.w) * 0.5f + x0.w;
            o1.x = (acc[i][4] + pb1.x) * 0.5f + x1.x;
            o1.y = (acc[i][5] + pb1.y) * 0.5f + x1.y;
            o1.z = (acc[i][6] + pb1.z) * 0.5f + x1.z;
            o1.w = (acc[i][7] + pb1.w) * 0.5f + x1.w;
            float* xp = g_x + (size_t)grow * CC + c0;
            ((float4*)xp)[0] = o0;
            ((float4*)xp)[1] = o1;
        }
    }
}

// ================= MLP via ldmatrix + mma.sync (bf16 HMMA) =================
__device__ __forceinline__ void ldsm_x4(uint32_t addr, uint32_t& r0, uint32_t& r1,
                                        uint32_t& r2, uint32_t& r3) {
    asm volatile("ldmatrix.sync.aligned.m8n8.x4.shared.b16 {%0,%1,%2,%3}, [%4];"
                 : "=r"(r0), "=r"(r1), "=r"(r2), "=r"(r3) : "r"(addr));
}
__device__ __forceinline__ void ldsm_x2_t(uint32_t addr, uint32_t& r0, uint32_t& r1) {
    asm volatile("ldmatrix.sync.aligned.m8n8.x2.trans.shared.b16 {%0,%1}, [%2];"
                 : "=r"(r0), "=r"(r1) : "r"(addr));
}
__device__ __forceinline__ void mma_bf16(float* d, const uint32_t* a, const uint32_t* b) {
    asm volatile(
        "mma.sync.aligned.m16n8k16.row.col.f32.bf16.bf16.f32 "
        "{%0,%1,%2,%3}, {%4,%5,%6,%7}, {%8,%9}, {%0,%1,%2,%3};"
        : "+f"(d[0]), "+f"(d[1]), "+f"(d[2]), "+f"(d[3])
        : "r"(a[0]), "r"(a[1]), "r"(a[2]), "r"(a[3]), "r"(b[0]), "r"(b[1]));
}

__global__ void __launch_bounds__(256)
mlp_hmma_kernel(const float* __restrict__ g2, const float* __restrict__ b2,
                const float* __restrict__ bb1, const float* __restrict__ bb2,
                float* __restrict__ out)
{
    extern __shared__ char smc[];
    const uint32_t sb = smem_u32(smc);
    const int tid  = threadIdx.x;
    const int wid  = tid >> 5;
    const int lane = tid & 31;
    const size_t row0 = (size_t)blockIdx.x * 128;

    const int wm = wid & 3;         // M warp coord (32 rows)
    const int wn = wid >> 2;        // N warp coord (64 cols)

    // ---- LN2 -> s_a (bf16, stride 136 elems) ----
    for (int it = 0; it < 16; ++it) {
        int r = wid + it * 8;
        float4 v = ((const float4*)(g_x + (row0 + r) * CC))[lane];
        float s  = v.x + v.y + v.z + v.w;
        float ss = v.x*v.x + v.y*v.y + v.z*v.z + v.w*v.w;
        #pragma unroll
        for (int o = 16; o; o >>= 1) {
            s  += __shfl_xor_sync(0xffffffffu, s,  o);
            ss += __shfl_xor_sync(0xffffffffu, ss, o);
        }
        float mean = s * (1.0f / 128.0f);
        float var  = ss * (1.0f / 128.0f) - mean * mean;
        float inv  = rsqrtf(var + 1e-5f);
        float4 gg = ((const float4*)g2)[lane];
        float4 bb = ((const float4*)b2)[lane];
        float o0 = (v.x - mean) * inv * gg.x + bb.x;
        float o1 = (v.y - mean) * inv * gg.y + bb.y;
        float o2 = (v.z - mean) * inv * gg.z + bb.z;
        float o3 = (v.w - mean) * inv * gg.w + bb.w;
        uint32_t p0, p1;
        asm("cvt.rn.bf16x2.f32 %0, %1, %2;" : "=r"(p0) : "f"(o1), "f"(o0));
        asm("cvt.rn.bf16x2.f32 %0, %1, %2;" : "=r"(p1) : "f"(o3), "f"(o2));
        *(uint2*)(smc + SA_OFF + r * SA_STRIDE_B + lane * 8) = make_uint2(p0, p1);
    }

    // ldmatrix per-thread source addresses
    //  A-frag (x4): rows m0 + (lane&15), col byte = (lane>>4)*16
    const uint32_t a_row = (uint32_t)(lane & 15);
    const uint32_t a_koff = (uint32_t)((lane >> 4) * 16);
    //  B-frag (x2.trans): rows k0 + (lane&15), col byte = n0*2
    const uint32_t b_row = (uint32_t)(lane & 15);

    // ================= GEMM1: 4 N-chunks of 128 =================
    for (int chunk = 0; chunk < 4; ++chunk) {
        __syncthreads();   // previous chunk's MMAs done reading s_b
        // coop load W1 chunk: rows 0..127, cols chunk*128..+127 (bf16)
        for (int idx = tid; idx < 2048; idx += 256) {
            int r = idx >> 4, c16 = idx & 15;
            uint4 v = *(const uint4*)(g_w1 + (size_t)r * MLPD + chunk * 128 + c16 * 8);
            *(uint4*)(smc + SB_OFF + r * SB_STRIDE_B + c16 * 16) = v;
        }
        __syncthreads();

        float acc[2][8][4];
        #pragma unroll
        for (int i = 0; i < 2; ++i)
            #pragma unroll
            for (int j = 0; j < 8; ++j)
                #pragma unroll
                for (int q = 0; q < 4; ++q) acc[i][j][q] = 0.0f;

        #pragma unroll
        for (int ks = 0; ks < 8; ++ks) {
            uint32_t af[2][4];
            #pragma unroll
            for (int mt = 0; mt < 2; ++mt) {
                uint32_t addr = sb + SA_OFF
                    + (wm * 32 + mt * 16 + a_row) * SA_STRIDE_B + ks * 32 + a_koff;
                ldsm_x4(addr, af[mt][0], af[mt][1], af[mt][2], af[mt][3]);
            }
            uint32_t bf[8][2];
            #pragma unroll
            for (int nt = 0; nt < 8; ++nt) {
                uint32_t addr = sb + SB_OFF
                    + (ks * 16 + b_row) * SB_STRIDE_B + (wn * 64 + nt * 8) * 2;
                ldsm_x2_t(addr, bf[nt][0], bf[nt][1]);
            }
            #pragma unroll
            for (int mt = 0; mt < 2; ++mt)
                #pragma unroll
                for (int nt = 0; nt < 8; ++nt)
                    mma_bf16(acc[mt][nt], af[mt], bf[nt]);
        }

        // epilogue: +bias, GELU, -> s_h (bf16, stride 520 elems)
        const int qr = lane >> 2, qc = (lane & 3) * 2;
        #pragma unroll
        for (int mt = 0; mt < 2; ++mt) {
            #pragma unroll
            for (int nt = 0; nt < 8; ++nt) {
                int col = chunk * 128 + wn * 64 + nt * 8 + qc;
                float bias0 = __ldg(bb1 + col), bias1 = __ldg(bb1 + col + 1);
                #pragma unroll
                for (int half = 0; half < 2; ++half) {
                    int r = wm * 32 + mt * 16 + qr + half * 8;
                    float v0 = acc[mt][nt][half * 2 + 0] + bias0;
                    float v1 = acc[mt][nt][half * 2 + 1] + bias1;
                    v0 = 0.5f * v0 * (1.0f + erff(v0 * 0.70710678118654752f));
                    v1 = 0.5f * v1 * (1.0f + erff(v1 * 0.70710678118654752f));
                    uint32_t pk;
                    asm("cvt.rn.bf16x2.f32 %0, %1, %2;" : "=r"(pk) : "f"(v1), "f"(v0));
                    *(uint32_t*)(smc + SH_OFF + r * SH_STRIDE_B + col * 2) = pk;
                }
            }
        }
    }

    // ================= GEMM2: K=512 in 4 sub-chunks of 128 =================
    float acc2[2][8][4];
    #pragma unroll
    for (int i = 0; i < 2; ++i)
        #pragma unroll
        for (int j = 0; j < 8; ++j)
            #pragma unroll
            for (int q = 0; q < 4; ++q) acc2[i][j][q] = 0.0f;

    for (int sub = 0; sub < 4; ++sub) {
        __syncthreads();   // protects s_b (prev MMAs / epilogue1 writes to s_h done)
        for (int idx = tid; idx < 2048; idx += 256) {
            int r = idx >> 4, c16 = idx & 15;
            uint4 v = *(const uint4*)(g_w2 + (size_t)(sub * 128 + r) * CC + c16 * 8);
            *(uint4*)(smc + SB_OFF + r * SB_STRIDE_B + c16 * 16) = v;
        }
        __syncthreads();

        #pragma unroll
        for (int ks = 0; ks < 8; ++ks) {
            uint32_t af[2][4];
            #pragma unroll
            for (int mt = 0; mt < 2; ++mt) {
                uint32_t addr = sb + SH_OFF
                    + (wm * 32 + mt * 16 + a_row) * SH_STRIDE_B
                    + (sub * 128 + ks * 16) * 2 + a_koff;
                ldsm_x4(addr, af[mt][0], af[mt][1], af[mt][2], af[mt][3]);
            }
            uint32_t bf[8][2];
            #pragma unroll
            for (int nt = 0; nt < 8; ++nt) {
                uint32_t addr = sb + SB_OFF
                    + (ks * 16 + b_row) * SB_STRIDE_B + (wn * 64 + nt * 8) * 2;
                ldsm_x2_t(addr, bf[nt][0], bf[nt][1]);
            }
            #pragma unroll
            for (int mt = 0; mt < 2; ++mt)
                #pragma unroll
                for (int nt = 0; nt < 8; ++nt)
                    mma_bf16(acc2[mt][nt], af[mt], bf[nt]);
        }
    }

    // ---- final epilogue: (acc + bb2)*0.5 + x -> out (direct float2 stores) ----
    {
        const int qr = lane >> 2, qc = (lane & 3) * 2;
        #pragma unroll
        for (int mt = 0; mt < 2; ++mt) {
            #pragma unroll
            for (int nt = 0; nt < 8; ++nt) {
                int col = wn * 64 + nt * 8 + qc;
                float bias0 = __ldg(bb2 + col), bias1 = __ldg(bb2 + col + 1);
                #pragma unroll
                for (int half = 0; half < 2; ++half) {
                    size_t r = row0 + wm * 32 + mt * 16 + qr + half * 8;
                    float2 xv = *(const float2*)(g_x + r * CC + col);
                    float2 o;
                    o.x = (acc2[mt][nt][half * 2 + 0] + bias0) * 0.5f + xv.x;
                    o.y = (acc2[mt][nt][half * 2 + 1] + bias1) * 0.5f + xv.y;
                    *(float2*)(out + r * CC + col) = o;
                }
            }
        }
    }
}

extern "C" void kernel_launch(void* const* d_in, const int* in_sizes, int n_in,
                              void* d_out, int out_size)
{
    const float* inputs     = (const float*)d_in[0];
    const float* qkv_w      = (const float*)d_in[1];
    const float* proj_w     = (const float*)d_in[2];
    const float* proj_b     = (const float*)d_in[3];
    const float* bias_table = (const float*)d_in[4];
    const float* g1         = (const float*)d_in[5];
    const float* b1         = (const float*)d_in[6];
    const float* g2         = (const float*)d_in[7];
    const float* b2         = (const float*)d_in[8];
    const float* w1         = (const float*)d_in[9];
    const float* bb1        = (const float*)d_in[10];
    const float* w2         = (const float*)d_in[11];
    const float* bb2        = (const float*)d_in[12];
    float* out = (float*)d_out;

    cudaFuncSetAttribute(attn_kernel,     cudaFuncAttributeMaxDynamicSharedMemorySize, SMEM1_BYTES);
    cudaFuncSetAttribute(mlp_hmma_kernel, cudaFuncAttributeMaxDynamicSharedMemorySize, SMEM_MLP);

    attn_kernel<<<RB * 512, 256, SMEM1_BYTES>>>(inputs, qkv_w, proj_w, proj_b,
                                                bias_table, g1, b1);
    prep_kernel<<<512, 256>>>(w1, w2);
    mlp_hmma_kernel<<<TT / 128, 256, SMEM_MLP>>>(g2, b2, bb1, bb2, out);
}

// round 5
// speedup vs baseline: 3.1980x; 1.3611x over previous
#include <cuda_runtime.h>
#include <cuda_bf16.h>
#include <math.h>
#include <stdint.h>

#define RB    8
#define RR    32
#define CC    128
#define HH    4
#define HDIM  32
#define NN    64
#define TT    (RB*RR*RR*RR)   // 262144 tokens
#define MLPD  512

// ---------------- device scratch ----------------
__device__ float g_x[(size_t)TT * CC];
__device__ __nv_bfloat16 g_qkvw[CC * 384];     // [128 K][384 N]
__device__ __nv_bfloat16 g_projw[CC * CC];     // [128 K][128 N]
__device__ __nv_bfloat16 g_w1[CC * MLPD];      // [128 K][512 N]
__device__ __nv_bfloat16 g_w2[MLPD * CC];      // [512 K][128 N]

__device__ __forceinline__ uint32_t smem_u32(const void* p) {
    uint32_t a;
    asm("{ .reg .u64 t; cvta.to.shared.u64 t, %1; cvt.u32.u64 %0, t; }" : "=r"(a) : "l"(p));
    return a;
}
__device__ __forceinline__ void ldsm_x4(uint32_t addr, uint32_t& r0, uint32_t& r1,
                                        uint32_t& r2, uint32_t& r3) {
    asm volatile("ldmatrix.sync.aligned.m8n8.x4.shared.b16 {%0,%1,%2,%3}, [%4];"
                 : "=r"(r0), "=r"(r1), "=r"(r2), "=r"(r3) : "r"(addr));
}
__device__ __forceinline__ void ldsm_x2_t(uint32_t addr, uint32_t& r0, uint32_t& r1) {
    asm volatile("ldmatrix.sync.aligned.m8n8.x2.trans.shared.b16 {%0,%1}, [%2];"
                 : "=r"(r0), "=r"(r1) : "r"(addr));
}
__device__ __forceinline__ void mma_bf16(float* d, const uint32_t* a, const uint32_t* b) {
    asm volatile(
        "mma.sync.aligned.m16n8k16.row.col.f32.bf16.bf16.f32 "
        "{%0,%1,%2,%3}, {%4,%5,%6,%7}, {%8,%9}, {%0,%1,%2,%3};"
        : "+f"(d[0]), "+f"(d[1]), "+f"(d[2]), "+f"(d[3])
        : "r"(a[0]), "r"(a[1]), "r"(a[2]), "r"(a[3]), "r"(b[0]), "r"(b[1]));
}
// exact bf16x2 -> 2x fp32
__device__ __forceinline__ void bf2f(uint32_t p, float& lo, float& hi) {
    lo = __uint_as_float(p << 16);
    hi = __uint_as_float(p & 0xffff0000u);
}

// ---------------- attention kernel smem layout (bytes) ----------------
#define SA2_OFF   0                       // A (LN'd): 128 x 272B = 34816
#define SB2_OFF   34816                   // B chunk:  128 x 272B = 34816
#define SQKV_OFF  69632                   // QKV bf16: 128 x 784B = 100352
#define SAO_OFF   169984                  // attn out: 128 x 272B = 34816
#define SBIAS_OFF 204800                  // 484 floats = 1936
#define SINT_OFF  206736                  // lab[128] + row[128] ints = 1024
#define SMEM_ATT  207760
#define QKV_STRIDE_B 784                  // 392 bf16 elems

// ---------------- MLP smem layout (unchanged, passed R4) ----------------
#define SA_OFF 0
#define SB_OFF 34816
#define SH_OFF 69632
#define SMEM_MLP (SH_OFF + 133120)
#define SA_STRIDE_B 272
#define SB_STRIDE_B 272
#define SH_STRIDE_B 1040

// ================= prep: fp32 -> bf16 weights =================
__global__ void __launch_bounds__(256)
prep_kernel(const float* __restrict__ qkv_w, const float* __restrict__ proj_w,
            const float* __restrict__ w1, const float* __restrict__ w2)
{
    int idx = blockIdx.x * 256 + threadIdx.x;
    if (idx < 49152) {
        g_qkvw[idx] = __float2bfloat16(qkv_w[idx]);
    } else if (idx < 65536) {
        int j = idx - 49152;
        g_projw[j] = __float2bfloat16(proj_w[j]);
    } else if (idx < 131072) {
        int j = idx - 65536;
        g_w1[j] = __float2bfloat16(w1[j]);
    } else {
        int j = idx - 131072;
        g_w2[j] = __float2bfloat16(w2[j]);
    }
}

// ================= attention kernel: HMMA QKV/proj + scalar softmax ==========
__global__ void __launch_bounds__(256)
attn_kernel(const float* __restrict__ inputs, const float* __restrict__ proj_b,
            const float* __restrict__ bias_table,
            const float* __restrict__ g1, const float* __restrict__ b1)
{
    extern __shared__ char smc[];
    const uint32_t sb = smem_u32(smc);
    float* s_bias = (float*)(smc + SBIAS_OFF);
    int*   s_lab  = (int*)(smc + SINT_OFF);
    int*   s_row  = s_lab + 128;

    const int tid  = threadIdx.x;
    const int wid  = tid >> 5;
    const int lane = tid & 31;
    const int wm = wid & 3, wn = wid >> 2;

    for (int i = tid; i < 484; i += 256) s_bias[i] = bias_table[i];

    // ---------------- Phase A: gather + LN1 -> bf16 A ----------------
    for (int it = 0; it < 16; ++it) {
        int n  = wid + it * 8;               // 0..127 local row
        int gw = blockIdx.x * 2 + (n >> 6);  // global window
        int b  = gw >> 9;
        int w9 = gw & 511;
        int G1 = w9 >> 6, G2 = (w9 >> 3) & 7, G3 = w9 & 7;
        int nq = n & 63;
        int t1 = nq >> 4, t2 = (nq >> 2) & 3, t3 = nq & 3;
        int s1 = G1 * 4 + t1, s2 = G2 * 4 + t2, s3 = G3 * 4 + t3;
        int i1 = (s1 + 2) & 31, i2 = (s2 + 2) & 31, i3 = (s3 + 2) & 31;
        int grow = b * 32768 + i1 * 1024 + i2 * 32 + i3;

        float4 v = ((const float4*)(inputs + (size_t)grow * CC))[lane];
        float s  = v.x + v.y + v.z + v.w;
        float ss = v.x*v.x + v.y*v.y + v.z*v.z + v.w*v.w;
        #pragma unroll
        for (int o = 16; o; o >>= 1) {
            s  += __shfl_xor_sync(0xffffffffu, s,  o);
            ss += __shfl_xor_sync(0xffffffffu, ss, o);
        }
        float mean = s * (1.0f / 128.0f);
        float var  = ss * (1.0f / 128.0f) - mean * mean;
        float inv  = rsqrtf(var + 1e-5f);
        float4 gg = ((const float4*)g1)[lane];
        float4 bb = ((const float4*)b1)[lane];
        float o0 = (v.x - mean) * inv * gg.x + bb.x;
        float o1 = (v.y - mean) * inv * gg.y + bb.y;
        float o2 = (v.z - mean) * inv * gg.z + bb.z;
        float o3 = (v.w - mean) * inv * gg.w + bb.w;
        uint32_t p0, p1;
        asm("cvt.rn.bf16x2.f32 %0, %1, %2;" : "=r"(p0) : "f"(o1), "f"(o0));
        asm("cvt.rn.bf16x2.f32 %0, %1, %2;" : "=r"(p1) : "f"(o3), "f"(o2));
        *(uint2*)(smc + SA2_OFF + n * SA_STRIDE_B + lane * 8) = make_uint2(p0, p1);

        if (lane == 0) {
            s_row[n] = grow;
            int r1 = s1 < 28 ? 0 : (s1 < 30 ? 1 : 2);
            int r2 = s2 < 28 ? 0 : (s2 < 30 ? 1 : 2);
            int r3 = s3 < 28 ? 0 : (s3 < 30 ? 1 : 2);
            s_lab[n] = r1 * 9 + r2 * 3 + r3;
        }
    }

    const uint32_t a_row  = (uint32_t)(lane & 15);
    const uint32_t a_koff = (uint32_t)((lane >> 4) * 16);
    const uint32_t b_row  = (uint32_t)(lane & 15);
    const int qr = lane >> 2, qc = (lane & 3) * 2;

    // ---------------- Phase B: QKV GEMM (3 N-chunks of 128) ----------------
    for (int chunk = 0; chunk < 3; ++chunk) {
        __syncthreads();
        for (int idx = tid; idx < 2048; idx += 256) {
            int r = idx >> 4, c16 = idx & 15;
            uint4 v = *(const uint4*)(g_qkvw + (size_t)r * 384 + chunk * 128 + c16 * 8);
            *(uint4*)(smc + SB2_OFF + r * SB_STRIDE_B + c16 * 16) = v;
        }
        __syncthreads();

        float acc[2][8][4];
        #pragma unroll
        for (int i = 0; i < 2; ++i)
            #pragma unroll
            for (int j = 0; j < 8; ++j)
                #pragma unroll
                for (int q = 0; q < 4; ++q) acc[i][j][q] = 0.0f;

        #pragma unroll
        for (int ks = 0; ks < 8; ++ks) {
            uint32_t af[2][4];
            #pragma unroll
            for (int mt = 0; mt < 2; ++mt) {
                uint32_t addr = sb + SA2_OFF
                    + (wm * 32 + mt * 16 + a_row) * SA_STRIDE_B + ks * 32 + a_koff;
                ldsm_x4(addr, af[mt][0], af[mt][1], af[mt][2], af[mt][3]);
            }
            uint32_t bf[8][2];
            #pragma unroll
            for (int nt = 0; nt < 8; ++nt) {
                uint32_t addr = sb + SB2_OFF
                    + (ks * 16 + b_row) * SB_STRIDE_B + (wn * 64 + nt * 8) * 2;
                ldsm_x2_t(addr, bf[nt][0], bf[nt][1]);
            }
            #pragma unroll
            for (int mt = 0; mt < 2; ++mt)
                #pragma unroll
                for (int nt = 0; nt < 8; ++nt)
                    mma_bf16(acc[mt][nt], af[mt], bf[nt]);
        }

        const float scale = (chunk == 0) ? 0.17677669529663687f : 1.0f;
        #pragma unroll
        for (int mt = 0; mt < 2; ++mt)
            #pragma unroll
            for (int nt = 0; nt < 8; ++nt) {
                int col = chunk * 128 + wn * 64 + nt * 8 + qc;
                #pragma unroll
                for (int half = 0; half < 2; ++half) {
                    int r = wm * 32 + mt * 16 + qr + half * 8;
                    float v0 = acc[mt][nt][half * 2 + 0] * scale;
                    float v1 = acc[mt][nt][half * 2 + 1] * scale;
                    uint32_t pk;
                    asm("cvt.rn.bf16x2.f32 %0, %1, %2;" : "=r"(pk) : "f"(v1), "f"(v0));
                    *(uint32_t*)(smc + SQKV_OFF + r * QKV_STRIDE_B + col * 2) = pk;
                }
            }
    }
    __syncthreads();   // all QKV written; all s_b reads done

    // prefetch proj weights into s_b (hides LDG under softmax)
    for (int idx = tid; idx < 2048; idx += 256) {
        int r = idx >> 4, c16 = idx & 15;
        uint4 v = *(const uint4*)(g_projw + (size_t)r * CC + c16 * 8);
        *(uint4*)(smc + SB2_OFF + r * SB_STRIDE_B + c16 * 16) = v;
    }

    // ---------------- Phase C: scalar fp32 softmax (2 pairs/thread) --------
    for (int it = 0; it < 2; ++it) {
        const int p    = tid + it * 256;
        const int wloc = p >> 8;
        const int h    = (p >> 6) & 3;
        const int nq   = p & 63;
        const int rloc = wloc * 64 + nq;
        const int t1n = nq >> 4, t2n = (nq >> 2) & 3, t3n = nq & 3;
        const int labn   = s_lab[rloc];
        const int base_n = (t1n + 3) * 11 + (t2n + 3) + (t3n + 3);
        const float* bp  = s_bias + base_n * 4 + h;

        float q[32];
        {
            const uint4* qp = (const uint4*)(smc + SQKV_OFF + rloc * QKV_STRIDE_B + h * 64);
            #pragma unroll
            for (int i = 0; i < 4; ++i) {
                uint4 u = qp[i];
                bf2f(u.x, q[i*8+0], q[i*8+1]);
                bf2f(u.y, q[i*8+2], q[i*8+3]);
                bf2f(u.z, q[i*8+4], q[i*8+5]);
                bf2f(u.w, q[i*8+6], q[i*8+7]);
            }
        }

        float sc[64];
        float mx = -1e30f;
        #pragma unroll
        for (int m = 0; m < 64; ++m) {
            const uint4* kp = (const uint4*)(smc + SQKV_OFF
                + (wloc * 64 + m) * QKV_STRIDE_B + 256 + h * 64);
            float d = 0.0f;
            #pragma unroll
            for (int i = 0; i < 4; ++i) {
                uint4 u = kp[i];
                float k0, k1;
                bf2f(u.x, k0, k1); d += q[i*8+0]*k0 + q[i*8+1]*k1;
                bf2f(u.y, k0, k1); d += q[i*8+2]*k0 + q[i*8+3]*k1;
                bf2f(u.z, k0, k1); d += q[i*8+4]*k0 + q[i*8+5]*k1;
                bf2f(u.w, k0, k1); d += q[i*8+6]*k0 + q[i*8+7]*k1;
            }
            const int off_m = 11 * (m >> 4) + ((m >> 2) & 3) + (m & 3);
            float msk = (labn == s_lab[wloc * 64 + m]) ? 0.0f : -100.0f;
            d += bp[-(off_m * 4)] + msk;
            sc[m] = d;
            mx = fmaxf(mx, d);
        }
        float sum = 0.0f;
        #pragma unroll
        for (int m = 0; m < 64; ++m) {
            float e = __expf(sc[m] - mx);
            sc[m] = e;
            sum += e;
        }
        const float invs = 1.0f / sum;

        float acc[32];
        #pragma unroll
        for (int i = 0; i < 32; ++i) acc[i] = 0.0f;
        #pragma unroll
        for (int m = 0; m < 64; ++m) {
            const float pr = sc[m] * invs;
            const uint4* vp = (const uint4*)(smc + SQKV_OFF
                + (wloc * 64 + m) * QKV_STRIDE_B + 512 + h * 64);
            #pragma unroll
            for (int i = 0; i < 4; ++i) {
                uint4 u = vp[i];
                float v0, v1;
                bf2f(u.x, v0, v1); acc[i*8+0] += pr*v0; acc[i*8+1] += pr*v1;
                bf2f(u.y, v0, v1); acc[i*8+2] += pr*v0; acc[i*8+3] += pr*v1;
                bf2f(u.z, v0, v1); acc[i*8+4] += pr*v0; acc[i*8+5] += pr*v1;
                bf2f(u.w, v0, v1); acc[i*8+6] += pr*v0; acc[i*8+7] += pr*v1;
            }
        }
        #pragma unroll
        for (int i = 0; i < 16; ++i) {
            uint32_t pk;
            asm("cvt.rn.bf16x2.f32 %0, %1, %2;" : "=r"(pk) : "f"(acc[2*i+1]), "f"(acc[2*i]));
            *(uint32_t*)(smc + SAO_OFF + rloc * SA_STRIDE_B + (h * 32 + 2 * i) * 2) = pk;
        }
    }
    __syncthreads();   // s_ao written; proj weights loaded

    // ---------------- Phase D: proj GEMM + residual -> g_x ----------------
    {
        float acc[2][8][4];
        #pragma unroll
        for (int i = 0; i < 2; ++i)
            #pragma unroll
            for (int j = 0; j < 8; ++j)
                #pragma unroll
                for (int q = 0; q < 4; ++q) acc[i][j][q] = 0.0f;

        #pragma unroll
        for (int ks = 0; ks < 8; ++ks) {
            uint32_t af[2][4];
            #pragma unroll
            for (int mt = 0; mt < 2; ++mt) {
                uint32_t addr = sb + SAO_OFF
                    + (wm * 32 + mt * 16 + a_row) * SA_STRIDE_B + ks * 32 + a_koff;
                ldsm_x4(addr, af[mt][0], af[mt][1], af[mt][2], af[mt][3]);
            }
            uint32_t bf[8][2];
            #pragma unroll
            for (int nt = 0; nt < 8; ++nt) {
                uint32_t addr = sb + SB2_OFF
                    + (ks * 16 + b_row) * SB_STRIDE_B + (wn * 64 + nt * 8) * 2;
                ldsm_x2_t(addr, bf[nt][0], bf[nt][1]);
            }
            #pragma unroll
            for (int mt = 0; mt < 2; ++mt)
                #pragma unroll
                for (int nt = 0; nt < 8; ++nt)
                    mma_bf16(acc[mt][nt], af[mt], bf[nt]);
        }

        #pragma unroll
        for (int mt = 0; mt < 2; ++mt)
            #pragma unroll
            for (int nt = 0; nt < 8; ++nt) {
                int col = wn * 64 + nt * 8 + qc;
                float pb0 = __ldg(proj_b + col), pb1 = __ldg(proj_b + col + 1);
                #pragma unroll
                for (int half = 0; half < 2; ++half) {
                    int r = wm * 32 + mt * 16 + qr + half * 8;
                    int grow = s_row[r];
                    float2 xv = *(const float2*)(inputs + (size_t)grow * CC + col);
                    float2 o;
                    o.x = (acc[mt][nt][half * 2 + 0] + pb0) * 0.5f + xv.x;
                    o.y = (acc[mt][nt][half * 2 + 1] + pb1) * 0.5f + xv.y;
                    *(float2*)(g_x + (size_t)grow * CC + col) = o;
                }
            }
    }
}

// ================= MLP via ldmatrix + mma.sync (unchanged, passed R4) ======
__global__ void __launch_bounds__(256)
mlp_hmma_kernel(const float* __restrict__ g2, const float* __restrict__ b2,
                const float* __restrict__ bb1, const float* __restrict__ bb2,
                float* __restrict__ out)
{
    extern __shared__ char smc[];
    const uint32_t sb = smem_u32(smc);
    const int tid  = threadIdx.x;
    const int wid  = tid >> 5;
    const int lane = tid & 31;
    const size_t row0 = (size_t)blockIdx.x * 128;

    const int wm = wid & 3;
    const int wn = wid >> 2;

    for (int it = 0; it < 16; ++it) {
        int r = wid + it * 8;
        float4 v = ((const float4*)(g_x + (row0 + r) * CC))[lane];
        float s  = v.x + v.y + v.z + v.w;
        float ss = v.x*v.x + v.y*v.y + v.z*v.z + v.w*v.w;
        #pragma unroll
        for (int o = 16; o; o >>= 1) {
            s  += __shfl_xor_sync(0xffffffffu, s,  o);
            ss += __shfl_xor_sync(0xffffffffu, ss, o);
        }
        float mean = s * (1.0f / 128.0f);
        float var  = ss * (1.0f / 128.0f) - mean * mean;
        float inv  = rsqrtf(var + 1e-5f);
        float4 gg = ((const float4*)g2)[lane];
        float4 bb = ((const float4*)b2)[lane];
        float o0 = (v.x - mean) * inv * gg.x + bb.x;
        float o1 = (v.y - mean) * inv * gg.y + bb.y;
        float o2 = (v.z - mean) * inv * gg.z + bb.z;
        float o3 = (v.w - mean) * inv * gg.w + bb.w;
        uint32_t p0, p1;
        asm("cvt.rn.bf16x2.f32 %0, %1, %2;" : "=r"(p0) : "f"(o1), "f"(o0));
        asm("cvt.rn.bf16x2.f32 %0, %1, %2;" : "=r"(p1) : "f"(o3), "f"(o2));
        *(uint2*)(smc + SA_OFF + r * SA_STRIDE_B + lane * 8) = make_uint2(p0, p1);
    }

    const uint32_t a_row = (uint32_t)(lane & 15);
    const uint32_t a_koff = (uint32_t)((lane >> 4) * 16);
    const uint32_t b_row = (uint32_t)(lane & 15);

    for (int chunk = 0; chunk < 4; ++chunk) {
        __syncthreads();
        for (int idx = tid; idx < 2048; idx += 256) {
            int r = idx >> 4, c16 = idx & 15;
            uint4 v = *(const uint4*)(g_w1 + (size_t)r * MLPD + chunk * 128 + c16 * 8);
            *(uint4*)(smc + SB_OFF + r * SB_STRIDE_B + c16 * 16) = v;
        }
        __syncthreads();

        float acc[2][8][4];
        #pragma unroll
        for (int i = 0; i < 2; ++i)
            #pragma unroll
            for (int j = 0; j < 8; ++j)
                #pragma unroll
                for (int q = 0; q < 4; ++q) acc[i][j][q] = 0.0f;

        #pragma unroll
        for (int ks = 0; ks < 8; ++ks) {
            uint32_t af[2][4];
            #pragma unroll
            for (int mt = 0; mt < 2; ++mt) {
                uint32_t addr = sb + SA_OFF
                    + (wm * 32 + mt * 16 + a_row) * SA_STRIDE_B + ks * 32 + a_koff;
                ldsm_x4(addr, af[mt][0], af[mt][1], af[mt][2], af[mt][3]);
            }
            uint32_t bf[8][2];
            #pragma unroll
            for (int nt = 0; nt < 8; ++nt) {
                uint32_t addr = sb + SB_OFF
                    + (ks * 16 + b_row) * SB_STRIDE_B + (wn * 64 + nt * 8) * 2;
                ldsm_x2_t(addr, bf[nt][0], bf[nt][1]);
            }
            #pragma unroll
            for (int mt = 0; mt < 2; ++mt)
                #pragma unroll
                for (int nt = 0; nt < 8; ++nt)
                    mma_bf16(acc[mt][nt], af[mt], bf[nt]);
        }

        const int qr = lane >> 2, qc = (lane & 3) * 2;
        #pragma unroll
        for (int mt = 0; mt < 2; ++mt) {
            #pragma unroll
            for (int nt = 0; nt < 8; ++nt) {
                int col = chunk * 128 + wn * 64 + nt * 8 + qc;
                float bias0 = __ldg(bb1 + col), bias1 = __ldg(bb1 + col + 1);
                #pragma unroll
                for (int half = 0; half < 2; ++half) {
                    int r = wm * 32 + mt * 16 + qr + half * 8;
                    float v0 = acc[mt][nt][half * 2 + 0] + bias0;
                    float v1 = acc[mt][nt][half * 2 + 1] + bias1;
                    v0 = 0.5f * v0 * (1.0f + erff(v0 * 0.70710678118654752f));
                    v1 = 0.5f * v1 * (1.0f + erff(v1 * 0.70710678118654752f));
                    uint32_t pk;
                    asm("cvt.rn.bf16x2.f32 %0, %1, %2;" : "=r"(pk) : "f"(v1), "f"(v0));
                    *(uint32_t*)(smc + SH_OFF + r * SH_STRIDE_B + col * 2) = pk;
                }
            }
        }
    }

    float acc2[2][8][4];
    #pragma unroll
    for (int i = 0; i < 2; ++i)
        #pragma unroll
        for (int j = 0; j < 8; ++j)
            #pragma unroll
            for (int q = 0; q < 4; ++q) acc2[i][j][q] = 0.0f;

    for (int sub = 0; sub < 4; ++sub) {
        __syncthreads();
        for (int idx = tid; idx < 2048; idx += 256) {
            int r = idx >> 4, c16 = idx & 15;
            uint4 v = *(const uint4*)(g_w2 + (size_t)(sub * 128 + r) * CC + c16 * 8);
            *(uint4*)(smc + SB_OFF + r * SB_STRIDE_B + c16 * 16) = v;
        }
        __syncthreads();

        #pragma unroll
        for (int ks = 0; ks < 8; ++ks) {
            uint32_t af[2][4];
            #pragma unroll
            for (int mt = 0; mt < 2; ++mt) {
                uint32_t addr = sb + SH_OFF
                    + (wm * 32 + mt * 16 + a_row) * SH_STRIDE_B
                    + (sub * 128 + ks * 16) * 2 + a_koff;
                ldsm_x4(addr, af[mt][0], af[mt][1], af[mt][2], af[mt][3]);
            }
            uint32_t bf[8][2];
            #pragma unroll
            for (int nt = 0; nt < 8; ++nt) {
                uint32_t addr = sb + SB_OFF
                    + (ks * 16 + b_row) * SB_STRIDE_B + (wn * 64 + nt * 8) * 2;
                ldsm_x2_t(addr, bf[nt][0], bf[nt][1]);
            }
            #pragma unroll
            for (int mt = 0; mt < 2; ++mt)
                #pragma unroll
                for (int nt = 0; nt < 8; ++nt)
                    mma_bf16(acc2[mt][nt], af[mt], bf[nt]);
        }
    }

    {
        const int qr = lane >> 2, qc = (lane & 3) * 2;
        #pragma unroll
        for (int mt = 0; mt < 2; ++mt) {
            #pragma unroll
            for (int nt = 0; nt < 8; ++nt) {
                int col = wn * 64 + nt * 8 + qc;
                float bias0 = __ldg(bb2 + col), bias1 = __ldg(bb2 + col + 1);
                #pragma unroll
                for (int half = 0; half < 2; ++half) {
                    size_t r = row0 + wm * 32 + mt * 16 + qr + half * 8;
                    float2 xv = *(const float2*)(g_x + r * CC + col);
                    float2 o;
                    o.x = (acc2[mt][nt][half * 2 + 0] + bias0) * 0.5f + xv.x;
                    o.y = (acc2[mt][nt][half * 2 + 1] + bias1) * 0.5f + xv.y;
                    *(float2*)(out + r * CC + col) = o;
                }
            }
        }
    }
}

extern "C" void kernel_launch(void* const* d_in, const int* in_sizes, int n_in,
                              void* d_out, int out_size)
{
    const float* inputs     = (const float*)d_in[0];
    const float* qkv_w      = (const float*)d_in[1];
    const float* proj_w     = (const float*)d_in[2];
    const float* proj_b     = (const float*)d_in[3];
    const float* bias_table = (const float*)d_in[4];
    const float* g1         = (const float*)d_in[5];
    const float* b1         = (const float*)d_in[6];
    const float* g2         = (const float*)d_in[7];
    const float* b2         = (const float*)d_in[8];
    const float* w1         = (const float*)d_in[9];
    const float* bb1        = (const float*)d_in[10];
    const float* w2         = (const float*)d_in[11];
    const float* bb2        = (const float*)d_in[12];
    float* out = (float*)d_out;

    cudaFuncSetAttribute(attn_kernel,     cudaFuncAttributeMaxDynamicSharedMemorySize, SMEM_ATT);
    cudaFuncSetAttribute(mlp_hmma_kernel, cudaFuncAttributeMaxDynamicSharedMemorySize, SMEM_MLP);

    prep_kernel<<<768, 256>>>(qkv_w, proj_w, w1, w2);
    attn_kernel<<<RB * 256, 256, SMEM_ATT>>>(inputs, proj_b, bias_table, g1, b1);
    mlp_hmma_kernel<<<TT / 128, 256, SMEM_MLP>>>(g2, b2, bb1, bb2, out);
}

// round 8
// speedup vs baseline: 6.2525x; 1.9551x over previous
#include <cuda_runtime.h>
#include <cuda_bf16.h>
#include <math.h>
#include <stdint.h>

#define RB    8
#define RR    32
#define CC    128
#define HH    4
#define HDIM  32
#define NN    64
#define TT    (RB*RR*RR*RR)   // 262144 tokens
#define MLPD  512

// ---------------- device scratch ----------------
__device__ float g_x[(size_t)TT * CC];
__device__ __nv_bfloat16 g_qkvw[CC * 384];     // [128 K][384 N]
__device__ __nv_bfloat16 g_projw[CC * CC];     // [128 K][128 N]
__device__ __nv_bfloat16 g_w1[CC * MLPD];      // [128 K][512 N]
__device__ __nv_bfloat16 g_w2[MLPD * CC];      // [512 K][128 N]

__device__ __forceinline__ uint32_t smem_u32(const void* p) {
    uint32_t a;
    asm("{ .reg .u64 t; cvta.to.shared.u64 t, %1; cvt.u32.u64 %0, t; }" : "=r"(a) : "l"(p));
    return a;
}
__device__ __forceinline__ void ldsm_x4(uint32_t addr, uint32_t& r0, uint32_t& r1,
                                        uint32_t& r2, uint32_t& r3) {
    asm volatile("ldmatrix.sync.aligned.m8n8.x4.shared.b16 {%0,%1,%2,%3}, [%4];"
                 : "=r"(r0), "=r"(r1), "=r"(r2), "=r"(r3) : "r"(addr));
}
__device__ __forceinline__ void ldsm_x2(uint32_t addr, uint32_t& r0, uint32_t& r1) {
    asm volatile("ldmatrix.sync.aligned.m8n8.x2.shared.b16 {%0,%1}, [%2];"
                 : "=r"(r0), "=r"(r1) : "r"(addr));
}
__device__ __forceinline__ void ldsm_x2_t(uint32_t addr, uint32_t& r0, uint32_t& r1) {
    asm volatile("ldmatrix.sync.aligned.m8n8.x2.trans.shared.b16 {%0,%1}, [%2];"
                 : "=r"(r0), "=r"(r1) : "r"(addr));
}
__device__ __forceinline__ void mma_bf16(float* d, const uint32_t* a, const uint32_t* b) {
    asm volatile(
        "mma.sync.aligned.m16n8k16.row.col.f32.bf16.bf16.f32 "
        "{%0,%1,%2,%3}, {%4,%5,%6,%7}, {%8,%9}, {%0,%1,%2,%3};"
        : "+f"(d[0]), "+f"(d[1]), "+f"(d[2]), "+f"(d[3])
        : "r"(a[0]), "r"(a[1]), "r"(a[2]), "r"(a[3]), "r"(b[0]), "r"(b[1]));
}

// ---------------- attention kernel smem layout (bytes) ----------------
#define SA2_OFF   0                       // A (LN'd): 128 x 272B = 34816 ; reused as P (warps 0-3)
#define SB2_OFF   34816                   // B chunk:  128 x 272B = 34816
#define SQKV_OFF  69632                   // QKV bf16: 128 x 784B = 100352
#define SAO_OFF   169984                  // attn out: 128 x 272B = 34816 ; first reused as P (warps 4-7)
#define SBIAS_OFF 204800                  // 484 floats
#define SINT_OFF  206736                  // lab[128] + row[128]
#define SMEM_ATT  207760
#define QKV_STRIDE_B 784

// ---------------- MLP smem layout (unchanged) ----------------
#define SA_OFF 0
#define SB_OFF 34816
#define SH_OFF 69632
#define SMEM_MLP (SH_OFF + 133120)
#define SA_STRIDE_B 272
#define SB_STRIDE_B 272
#define SH_STRIDE_B 1040

// ================= prep: fp32 -> bf16 weights =================
__global__ void __launch_bounds__(256)
prep_kernel(const float* __restrict__ qkv_w, const float* __restrict__ proj_w,
            const float* __restrict__ w1, const float* __restrict__ w2)
{
    int idx = blockIdx.x * 256 + threadIdx.x;
    if (idx < 49152) {
        g_qkvw[idx] = __float2bfloat16(qkv_w[idx]);
    } else if (idx < 65536) {
        int j = idx - 49152;
        g_projw[j] = __float2bfloat16(proj_w[j]);
    } else if (idx < 131072) {
        int j = idx - 65536;
        g_w1[j] = __float2bfloat16(w1[j]);
    } else {
        int j = idx - 131072;
        g_w2[j] = __float2bfloat16(w2[j]);
    }
}

// ================= attention kernel: fully tensorized =================
__global__ void __launch_bounds__(256)
attn_kernel(const float* __restrict__ inputs, const float* __restrict__ proj_b,
            const float* __restrict__ bias_table,
            const float* __restrict__ g1, const float* __restrict__ b1)
{
    extern __shared__ char smc[];
    const uint32_t sb = smem_u32(smc);
    float* s_bias = (float*)(smc + SBIAS_OFF);
    int*   s_lab  = (int*)(smc + SINT_OFF);
    int*   s_row  = s_lab + 128;

    const int tid  = threadIdx.x;
    const int wid  = tid >> 5;
    const int lane = tid & 31;
    const int wm = wid & 3, wn = wid >> 2;

    for (int i = tid; i < 484; i += 256) s_bias[i] = bias_table[i];

    // ---------------- Phase A: gather + LN1 -> bf16 A ----------------
    for (int it = 0; it < 16; ++it) {
        int n  = wid + it * 8;
        int gw = blockIdx.x * 2 + (n >> 6);
        int b  = gw >> 9;
        int w9 = gw & 511;
        int G1 = w9 >> 6, G2 = (w9 >> 3) & 7, G3 = w9 & 7;
        int nq = n & 63;
        int t1 = nq >> 4, t2 = (nq >> 2) & 3, t3 = nq & 3;
        int s1 = G1 * 4 + t1, s2 = G2 * 4 + t2, s3 = G3 * 4 + t3;
        int i1 = (s1 + 2) & 31, i2 = (s2 + 2) & 31, i3 = (s3 + 2) & 31;
        int grow = b * 32768 + i1 * 1024 + i2 * 32 + i3;

        float4 v = ((const float4*)(inputs + (size_t)grow * CC))[lane];
        float s  = v.x + v.y + v.z + v.w;
        float ss = v.x*v.x + v.y*v.y + v.z*v.z + v.w*v.w;
        #pragma unroll
        for (int o = 16; o; o >>= 1) {
            s  += __shfl_xor_sync(0xffffffffu, s,  o);
            ss += __shfl_xor_sync(0xffffffffu, ss, o);
        }
        float mean = s * (1.0f / 128.0f);
        float var  = ss * (1.0f / 128.0f) - mean * mean;
        float inv  = rsqrtf(var + 1e-5f);
        float4 gg = ((const float4*)g1)[lane];
        float4 bb = ((const float4*)b1)[lane];
        float o0 = (v.x - mean) * inv * gg.x + bb.x;
        float o1 = (v.y - mean) * inv * gg.y + bb.y;
        float o2 = (v.z - mean) * inv * gg.z + bb.z;
        float o3 = (v.w - mean) * inv * gg.w + bb.w;
        uint32_t p0, p1;
        asm("cvt.rn.bf16x2.f32 %0, %1, %2;" : "=r"(p0) : "f"(o1), "f"(o0));
        asm("cvt.rn.bf16x2.f32 %0, %1, %2;" : "=r"(p1) : "f"(o3), "f"(o2));
        *(uint2*)(smc + SA2_OFF + n * SA_STRIDE_B + lane * 8) = make_uint2(p0, p1);

        if (lane == 0) {
            s_row[n] = grow;
            int r1 = s1 < 28 ? 0 : (s1 < 30 ? 1 : 2);
            int r2 = s2 < 28 ? 0 : (s2 < 30 ? 1 : 2);
            int r3 = s3 < 28 ? 0 : (s3 < 30 ? 1 : 2);
            s_lab[n] = r1 * 9 + r2 * 3 + r3;
        }
    }

    const uint32_t a_row  = (uint32_t)(lane & 15);
    const uint32_t a_koff = (uint32_t)((lane >> 4) * 16);
    const uint32_t b_row  = (uint32_t)(lane & 15);
    const int qr = lane >> 2, qc = (lane & 3) * 2;

    // ---------------- Phase B: QKV GEMM (3 N-chunks of 128) ----------------
    for (int chunk = 0; chunk < 3; ++chunk) {
        __syncthreads();
        for (int idx = tid; idx < 2048; idx += 256) {
            int r = idx >> 4, c16 = idx & 15;
            uint4 v = *(const uint4*)(g_qkvw + (size_t)r * 384 + chunk * 128 + c16 * 8);
            *(uint4*)(smc + SB2_OFF + r * SB_STRIDE_B + c16 * 16) = v;
        }
        __syncthreads();

        float acc[2][8][4];
        #pragma unroll
        for (int i = 0; i < 2; ++i)
            #pragma unroll
            for (int j = 0; j < 8; ++j)
                #pragma unroll
                for (int q = 0; q < 4; ++q) acc[i][j][q] = 0.0f;

        #pragma unroll
        for (int ks = 0; ks < 8; ++ks) {
            uint32_t af[2][4];
            #pragma unroll
            for (int mt = 0; mt < 2; ++mt) {
                uint32_t addr = sb + SA2_OFF
                    + (wm * 32 + mt * 16 + a_row) * SA_STRIDE_B + ks * 32 + a_koff;
                ldsm_x4(addr, af[mt][0], af[mt][1], af[mt][2], af[mt][3]);
            }
            uint32_t bf[8][2];
            #pragma unroll
            for (int nt = 0; nt < 8; ++nt) {
                uint32_t addr = sb + SB2_OFF
                    + (ks * 16 + b_row) * SB_STRIDE_B + (wn * 64 + nt * 8) * 2;
                ldsm_x2_t(addr, bf[nt][0], bf[nt][1]);
            }
            #pragma unroll
            for (int mt = 0; mt < 2; ++mt)
                #pragma unroll
                for (int nt = 0; nt < 8; ++nt)
                    mma_bf16(acc[mt][nt], af[mt], bf[nt]);
        }

        const float scale = (chunk == 0) ? 0.17677669529663687f : 1.0f;
        #pragma unroll
        for (int mt = 0; mt < 2; ++mt)
            #pragma unroll
            for (int nt = 0; nt < 8; ++nt) {
                int col = chunk * 128 + wn * 64 + nt * 8 + qc;
                #pragma unroll
                for (int half = 0; half < 2; ++half) {
                    int r = wm * 32 + mt * 16 + qr + half * 8;
                    float v0 = acc[mt][nt][half * 2 + 0] * scale;
                    float v1 = acc[mt][nt][half * 2 + 1] * scale;
                    uint32_t pk;
                    asm("cvt.rn.bf16x2.f32 %0, %1, %2;" : "=r"(pk) : "f"(v1), "f"(v0));
                    *(uint32_t*)(smc + SQKV_OFF + r * QKV_STRIDE_B + col * 2) = pk;
                }
            }
    }
    __syncthreads();   // QKV complete; SA2/SB2 reads done

    // prefetch proj weights into SB2 (P lives in SA2/SAO, SB2 stays intact)
    for (int idx = tid; idx < 2048; idx += 256) {
        int r = idx >> 4, c16 = idx & 15;
        uint4 v = *(const uint4*)(g_projw + (size_t)r * CC + c16 * 8);
        *(uint4*)(smc + SB2_OFF + r * SB_STRIDE_B + c16 * 16) = v;
    }

    // ---------------- Phase C: tensorized attention (warp = window x head) --
    {
        const int wloc = wid >> 2;
        const int h    = wid & 3;
        const uint32_t qkvb = sb + SQKV_OFF;
        const uint32_t p_off = (wid < 4) ? (uint32_t)(SA2_OFF + wid * 8192)
                                         : (uint32_t)(SAO_OFF + (wid - 4) * 8192);
        const uint32_t prow = sb + p_off;        // smem-window address (ldmatrix)
        char* const prow_ptr = smc + p_off;      // generic pointer (stores)

        // hoisted column metadata (16 cols per thread)
        int   labc[16];
        int   offc[16];
        #pragma unroll
        for (int nt = 0; nt < 8; ++nt)
            #pragma unroll
            for (int e = 0; e < 2; ++e) {
                int c = nt * 8 + qc + e;
                labc[nt * 2 + e] = s_lab[wloc * 64 + c];
                offc[nt * 2 + e] = 11 * (c >> 4) + ((c >> 2) & 3) + (c & 3);
            }

        // --- S = Q K^T, softmax, P -> swizzled smem (two 32-row halves) ---
        for (int mh = 0; mh < 2; ++mh) {
            float S[2][8][4];
            #pragma unroll
            for (int i = 0; i < 2; ++i)
                #pragma unroll
                for (int j = 0; j < 8; ++j)
                    #pragma unroll
                    for (int q = 0; q < 4; ++q) S[i][j][q] = 0.0f;

            #pragma unroll
            for (int ks = 0; ks < 2; ++ks) {
                uint32_t af[2][4];
                #pragma unroll
                for (int mt = 0; mt < 2; ++mt) {
                    uint32_t addr = qkvb
                        + (wloc * 64 + mh * 32 + mt * 16 + a_row) * QKV_STRIDE_B
                        + h * 64 + ks * 32 + a_koff;
                    ldsm_x4(addr, af[mt][0], af[mt][1], af[mt][2], af[mt][3]);
                }
                uint32_t bf[8][2];
                #pragma unroll
                for (int nt = 0; nt < 8; ++nt) {
                    uint32_t addr = qkvb
                        + (wloc * 64 + nt * 8 + (lane & 7)) * QKV_STRIDE_B
                        + 256 + h * 64 + ks * 32 + ((lane >> 3) & 1) * 16;
                    ldsm_x2(addr, bf[nt][0], bf[nt][1]);
                }
                #pragma unroll
                for (int mt = 0; mt < 2; ++mt)
                    #pragma unroll
                    for (int nt = 0; nt < 8; ++nt)
                        mma_bf16(S[mt][nt], af[mt], bf[nt]);
            }

            // bias + mask + softmax per row (row group = 4 threads, shfl 1,2)
            #pragma unroll
            for (int mt = 0; mt < 2; ++mt) {
                #pragma unroll
                for (int half = 0; half < 2; ++half) {
                    int nq = mh * 32 + mt * 16 + qr + half * 8;
                    int labn = s_lab[wloc * 64 + nq];
                    int base_n = ((nq >> 4) + 3) * 11 + ((nq >> 2) & 3) + (nq & 3) + 6;

                    float rmax = -1e30f;
                    #pragma unroll
                    for (int nt = 0; nt < 8; ++nt)
                        #pragma unroll
                        for (int e = 0; e < 2; ++e) {
                            float v = S[mt][nt][half * 2 + e]
                                + s_bias[(base_n - offc[nt * 2 + e]) * 4 + h];
                            if (labn != labc[nt * 2 + e]) v -= 100.0f;
                            S[mt][nt][half * 2 + e] = v;
                            rmax = fmaxf(rmax, v);
                        }
                    rmax = fmaxf(rmax, __shfl_xor_sync(0xffffffffu, rmax, 1));
                    rmax = fmaxf(rmax, __shfl_xor_sync(0xffffffffu, rmax, 2));

                    float rsum = 0.0f;
                    #pragma unroll
                    for (int nt = 0; nt < 8; ++nt)
                        #pragma unroll
                        for (int e = 0; e < 2; ++e) {
                            float ev = __expf(S[mt][nt][half * 2 + e] - rmax);
                            S[mt][nt][half * 2 + e] = ev;
                            rsum += ev;
                        }
                    rsum += __shfl_xor_sync(0xffffffffu, rsum, 1);
                    rsum += __shfl_xor_sync(0xffffffffu, rsum, 2);
                    float invs = 1.0f / rsum;

                    // store P row (bf16, swizzled: block ^= row&7) via generic ptr
                    int prow_i = nq;
                    #pragma unroll
                    for (int nt = 0; nt < 8; ++nt) {
                        float p0 = S[mt][nt][half * 2 + 0] * invs;
                        float p1 = S[mt][nt][half * 2 + 1] * invs;
                        uint32_t pk;
                        asm("cvt.rn.bf16x2.f32 %0, %1, %2;" : "=r"(pk) : "f"(p1), "f"(p0));
                        int c = nt * 8 + qc;
                        uint32_t byte = prow_i * 128
                            + (uint32_t)(((c >> 3) ^ (prow_i & 7)) * 16) + (c & 7) * 2;
                        *(uint32_t*)(prow_ptr + byte) = pk;
                    }
                }
            }
        }
        __syncwarp();

        // --- O = P V (64x32, K=64) ---
        float O[4][4][4];
        #pragma unroll
        for (int i = 0; i < 4; ++i)
            #pragma unroll
            for (int j = 0; j < 4; ++j)
                #pragma unroll
                for (int q = 0; q < 4; ++q) O[i][j][q] = 0.0f;

        #pragma unroll
        for (int ks = 0; ks < 4; ++ks) {
            uint32_t af[4][4];
            #pragma unroll
            for (int mt = 0; mt < 4; ++mt) {
                uint32_t r = mt * 16 + a_row;
                uint32_t blk = (uint32_t)((ks * 2 + (lane >> 4)) ^ (r & 7));
                ldsm_x4(prow + r * 128 + blk * 16,
                        af[mt][0], af[mt][1], af[mt][2], af[mt][3]);
            }
            uint32_t bf[4][2];
            #pragma unroll
            for (int nt = 0; nt < 4; ++nt) {
                uint32_t addr = qkvb
                    + (wloc * 64 + ks * 16 + b_row) * QKV_STRIDE_B
                    + 512 + h * 64 + nt * 16;
                ldsm_x2_t(addr, bf[nt][0], bf[nt][1]);
            }
            #pragma unroll
            for (int mt = 0; mt < 4; ++mt)
                #pragma unroll
                for (int nt = 0; nt < 4; ++nt)
                    mma_bf16(O[mt][nt], af[mt], bf[nt]);
        }
        __syncthreads();   // all P reads done before SAO overwritten

        #pragma unroll
        for (int mt = 0; mt < 4; ++mt)
            #pragma unroll
            for (int nt = 0; nt < 4; ++nt) {
                int col = h * 32 + nt * 8 + qc;
                #pragma unroll
                for (int half = 0; half < 2; ++half) {
                    int r = wloc * 64 + mt * 16 + qr + half * 8;
                    uint32_t pk;
                    asm("cvt.rn.bf16x2.f32 %0, %1, %2;" : "=r"(pk)
                        : "f"(O[mt][nt][half * 2 + 1]), "f"(O[mt][nt][half * 2 + 0]));
                    *(uint32_t*)(smc + SAO_OFF + r * SA_STRIDE_B + col * 2) = pk;
                }
            }
    }
    __syncthreads();   // SAO complete; proj weights loaded

    // ---------------- Phase D: proj GEMM + residual -> g_x ----------------
    {
        float acc[2][8][4];
        #pragma unroll
        for (int i = 0; i < 2; ++i)
            #pragma unroll
            for (int j = 0; j < 8; ++j)
                #pragma unroll
                for (int q = 0; q < 4; ++q) acc[i][j][q] = 0.0f;

        #pragma unroll
        for (int ks = 0; ks < 8; ++ks) {
            uint32_t af[2][4];
            #pragma unroll
            for (int mt = 0; mt < 2; ++mt) {
                uint32_t addr = sb + SAO_OFF
                    + (wm * 32 + mt * 16 + a_row) * SA_STRIDE_B + ks * 32 + a_koff;
                ldsm_x4(addr, af[mt][0], af[mt][1], af[mt][2], af[mt][3]);
            }
            uint32_t bf[8][2];
            #pragma unroll
            for (int nt = 0; nt < 8; ++nt) {
                uint32_t addr = sb + SB2_OFF
                    + (ks * 16 + b_row) * SB_STRIDE_B + (wn * 64 + nt * 8) * 2;
                ldsm_x2_t(addr, bf[nt][0], bf[nt][1]);
            }
            #pragma unroll
            for (int mt = 0; mt < 2; ++mt)
                #pragma unroll
                for (int nt = 0; nt < 8; ++nt)
                    mma_bf16(acc[mt][nt], af[mt], bf[nt]);
        }

        #pragma unroll
        for (int mt = 0; mt < 2; ++mt)
            #pragma unroll
            for (int nt = 0; nt < 8; ++nt) {
                int col = wn * 64 + nt * 8 + qc;
                float pb0 = __ldg(proj_b + col), pb1 = __ldg(proj_b + col + 1);
                #pragma unroll
                for (int half = 0; half < 2; ++half) {
                    int r = wm * 32 + mt * 16 + qr + half * 8;
                    int grow = s_row[r];
                    float2 xv = *(const float2*)(inputs + (size_t)grow * CC + col);
                    float2 o;
                    o.x = (acc[mt][nt][half * 2 + 0] + pb0) * 0.5f + xv.x;
                    o.y = (acc[mt][nt][half * 2 + 1] + pb1) * 0.5f + xv.y;
                    *(float2*)(g_x + (size_t)grow * CC + col) = o;
                }
            }
    }
}

// ================= MLP via ldmatrix + mma.sync (unchanged) =================
__global__ void __launch_bounds__(256)
mlp_hmma_kernel(const float* __restrict__ g2, const float* __restrict__ b2,
                const float* __restrict__ bb1, const float* __restrict__ bb2,
                float* __restrict__ out)
{
    extern __shared__ char smc[];
    const uint32_t sb = smem_u32(smc);
    const int tid  = threadIdx.x;
    const int wid  = tid >> 5;
    const int lane = tid & 31;
    const size_t row0 = (size_t)blockIdx.x * 128;

    const int wm = wid & 3;
    const int wn = wid >> 2;

    for (int it = 0; it < 16; ++it) {
        int r = wid + it * 8;
        float4 v = ((const float4*)(g_x + (row0 + r) * CC))[lane];
        float s  = v.x + v.y + v.z + v.w;
        float ss = v.x*v.x + v.y*v.y + v.z*v.z + v.w*v.w;
        #pragma unroll
        for (int o = 16; o; o >>= 1) {
            s  += __shfl_xor_sync(0xffffffffu, s,  o);
            ss += __shfl_xor_sync(0xffffffffu, ss, o);
        }
        float mean = s * (1.0f / 128.0f);
        float var  = ss * (1.0f / 128.0f) - mean * mean;
        float inv  = rsqrtf(var + 1e-5f);
        float4 gg = ((const float4*)g2)[lane];
        float4 bb = ((const float4*)b2)[lane];
        float o0 = (v.x - mean) * inv * gg.x + bb.x;
        float o1 = (v.y - mean) * inv * gg.y + bb.y;
        float o2 = (v.z - mean) * inv * gg.z + bb.z;
        float o3 = (v.w - mean) * inv * gg.w + bb.w;
        uint32_t p0, p1;
        asm("cvt.rn.bf16x2.f32 %0, %1, %2;" : "=r"(p0) : "f"(o1), "f"(o0));
        asm("cvt.rn.bf16x2.f32 %0, %1, %2;" : "=r"(p1) : "f"(o3), "f"(o2));
        *(uint2*)(smc + SA_OFF + r * SA_STRIDE_B + lane * 8) = make_uint2(p0, p1);
    }

    const uint32_t a_row = (uint32_t)(lane & 15);
    const uint32_t a_koff = (uint32_t)((lane >> 4) * 16);
    const uint32_t b_row = (uint32_t)(lane & 15);

    for (int chunk = 0; chunk < 4; ++chunk) {
        __syncthreads();
        for (int idx = tid; idx < 2048; idx += 256) {
            int r = idx >> 4, c16 = idx & 15;
            uint4 v = *(const uint4*)(g_w1 + (size_t)r * MLPD + chunk * 128 + c16 * 8);
            *(uint4*)(smc + SB_OFF + r * SB_STRIDE_B + c16 * 16) = v;
        }
        __syncthreads();

        float acc[2][8][4];
        #pragma unroll
        for (int i = 0; i < 2; ++i)
            #pragma unroll
            for (int j = 0; j < 8; ++j)
                #pragma unroll
                for (int q = 0; q < 4; ++q) acc[i][j][q] = 0.0f;

        #pragma unroll
        for (int ks = 0; ks < 8; ++ks) {
            uint32_t af[2][4];
            #pragma unroll
            for (int mt = 0; mt < 2; ++mt) {
                uint32_t addr = sb + SA_OFF
                    + (wm * 32 + mt * 16 + a_row) * SA_STRIDE_B + ks * 32 + a_koff;
                ldsm_x4(addr, af[mt][0], af[mt][1], af[mt][2], af[mt][3]);
            }
            uint32_t bf[8][2];
            #pragma unroll
            for (int nt = 0; nt < 8; ++nt) {
                uint32_t addr = sb + SB_OFF
                    + (ks * 16 + b_row) * SB_STRIDE_B + (wn * 64 + nt * 8) * 2;
                ldsm_x2_t(addr, bf[nt][0], bf[nt][1]);
            }
            #pragma unroll
            for (int mt = 0; mt < 2; ++mt)
                #pragma unroll
                for (int nt = 0; nt < 8; ++nt)
                    mma_bf16(acc[mt][nt], af[mt], bf[nt]);
        }

        const int qr = lane >> 2, qc = (lane & 3) * 2;
        #pragma unroll
        for (int mt = 0; mt < 2; ++mt) {
            #pragma unroll
            for (int nt = 0; nt < 8; ++nt) {
                int col = chunk * 128 + wn * 64 + nt * 8 + qc;
                float bias0 = __ldg(bb1 + col), bias1 = __ldg(bb1 + col + 1);
                #pragma unroll
                for (int half = 0; half < 2; ++half) {
                    int r = wm * 32 + mt * 16 + qr + half * 8;
                    float v0 = acc[mt][nt][half * 2 + 0] + bias0;
                    float v1 = acc[mt][nt][half * 2 + 1] + bias1;
                    v0 = 0.5f * v0 * (1.0f + erff(v0 * 0.70710678118654752f));
                    v1 = 0.5f * v1 * (1.0f + erff(v1 * 0.70710678118654752f));
                    uint32_t pk;
                    asm("cvt.rn.bf16x2.f32 %0, %1, %2;" : "=r"(pk) : "f"(v1), "f"(v0));
                    *(uint32_t*)(smc + SH_OFF + r * SH_STRIDE_B + col * 2) = pk;
                }
            }
        }
    }

    float acc2[2][8][4];
    #pragma unroll
    for (int i = 0; i < 2; ++i)
        #pragma unroll
        for (int j = 0; j < 8; ++j)
            #pragma unroll
            for (int q = 0; q < 4; ++q) acc2[i][j][q] = 0.0f;

    for (int sub = 0; sub < 4; ++sub) {
        __syncthreads();
        for (int idx = tid; idx < 2048; idx += 256) {
            int r = idx >> 4, c16 = idx & 15;
            uint4 v = *(const uint4*)(g_w2 + (size_t)(sub * 128 + r) * CC + c16 * 8);
            *(uint4*)(smc + SB_OFF + r * SB_STRIDE_B + c16 * 16) = v;
        }
        __syncthreads();

        #pragma unroll
        for (int ks = 0; ks < 8; ++ks) {
            uint32_t af[2][4];
            #pragma unroll
            for (int mt = 0; mt < 2; ++mt) {
                uint32_t addr = sb + SH_OFF
                    + (wm * 32 + mt * 16 + a_row) * SH_STRIDE_B
                    + (sub * 128 + ks * 16) * 2 + a_koff;
                ldsm_x4(addr, af[mt][0], af[mt][1], af[mt][2], af[mt][3]);
            }
            uint32_t bf[8][2];
            #pragma unroll
            for (int nt = 0; nt < 8; ++nt) {
                uint32_t addr = sb + SB_OFF
                    + (ks * 16 + b_row) * SB_STRIDE_B + (wn * 64 + nt * 8) * 2;
                ldsm_x2_t(addr, bf[nt][0], bf[nt][1]);
            }
            #pragma unroll
            for (int mt = 0; mt < 2; ++mt)
                #pragma unroll
                for (int nt = 0; nt < 8; ++nt)
                    mma_bf16(acc2[mt][nt], af[mt], bf[nt]);
        }
    }

    {
        const int qr = lane >> 2, qc = (lane & 3) * 2;
        #pragma unroll
        for (int mt = 0; mt < 2; ++mt) {
            #pragma unroll
            for (int nt = 0; nt < 8; ++nt) {
                int col = wn * 64 + nt * 8 + qc;
                float bias0 = __ldg(bb2 + col), bias1 = __ldg(bb2 + col + 1);
                #pragma unroll
                for (int half = 0; half < 2; ++half) {
                    size_t r = row0 + wm * 32 + mt * 16 + qr + half * 8;
                    float2 xv = *(const float2*)(g_x + r * CC + col);
                    float2 o;
                    o.x = (acc2[mt][nt][half * 2 + 0] + bias0) * 0.5f + xv.x;
                    o.y = (acc2[mt][nt][half * 2 + 1] + bias1) * 0.5f + xv.y;
                    *(float2*)(out + r * CC + col) = o;
                }
            }
        }
    }
}

extern "C" void kernel_launch(void* const* d_in, const int* in_sizes, int n_in,
                              void* d_out, int out_size)
{
    const float* inputs     = (const float*)d_in[0];
    const float* qkv_w      = (const float*)d_in[1];
    const float* proj_w     = (const float*)d_in[2];
    const float* proj_b     = (const float*)d_in[3];
    const float* bias_table = (const float*)d_in[4];
    const float* g1         = (const float*)d_in[5];
    const float* b1         = (const float*)d_in[6];
    const float* g2         = (const float*)d_in[7];
    const float* b2         = (const float*)d_in[8];
    const float* w1         = (const float*)d_in[9];
    const float* bb1        = (const float*)d_in[10];
    const float* w2         = (const float*)d_in[11];
    const float* bb2        = (const float*)d_in[12];
    float* out = (float*)d_out;

    cudaFuncSetAttribute(attn_kernel,     cudaFuncAttributeMaxDynamicSharedMemorySize, SMEM_ATT);
    cudaFuncSetAttribute(mlp_hmma_kernel, cudaFuncAttributeMaxDynamicSharedMemorySize, SMEM_MLP);

    prep_kernel<<<768, 256>>>(qkv_w, proj_w, w1, w2);
    attn_kernel<<<RB * 256, 256, SMEM_ATT>>>(inputs, proj_b, bias_table, g1, b1);
    mlp_hmma_kernel<<<TT / 128, 256, SMEM_MLP>>>(g2, b2, bb1, bb2, out);
}

// round 12
// speedup vs baseline: 7.0006x; 1.1196x over previous
#include <cuda_runtime.h>
#include <cuda_bf16.h>
#include <math.h>
#include <stdint.h>

#define RB    8
#define RR    32
#define CC    128
#define HH    4
#define HDIM  32
#define NN    64
#define TT    (RB*RR*RR*RR)   // 262144 tokens
#define MLPD  512

// ---------------- device scratch ----------------
__device__ float g_x[(size_t)TT * CC];
__device__ __nv_bfloat16 g_qkvw[CC * 384];     // [128 K][384 N]
__device__ __nv_bfloat16 g_projw[CC * CC];     // [128 K][128 N]
__device__ __nv_bfloat16 g_w1[CC * MLPD];      // [128 K][512 N]
__device__ __nv_bfloat16 g_w2[MLPD * CC];      // [512 K][128 N]

__device__ __forceinline__ uint32_t smem_u32(const void* p) {
    uint32_t a;
    asm("{ .reg .u64 t; cvta.to.shared.u64 t, %1; cvt.u32.u64 %0, t; }" : "=r"(a) : "l"(p));
    return a;
}
__device__ __forceinline__ void ldsm_x4(uint32_t addr, uint32_t& r0, uint32_t& r1,
                                        uint32_t& r2, uint32_t& r3) {
    asm volatile("ldmatrix.sync.aligned.m8n8.x4.shared.b16 {%0,%1,%2,%3}, [%4];"
                 : "=r"(r0), "=r"(r1), "=r"(r2), "=r"(r3) : "r"(addr));
}
__device__ __forceinline__ void ldsm_x2(uint32_t addr, uint32_t& r0, uint32_t& r1) {
    asm volatile("ldmatrix.sync.aligned.m8n8.x2.shared.b16 {%0,%1}, [%2];"
                 : "=r"(r0), "=r"(r1) : "r"(addr));
}
__device__ __forceinline__ void ldsm_x2_t(uint32_t addr, uint32_t& r0, uint32_t& r1) {
    asm volatile("ldmatrix.sync.aligned.m8n8.x2.trans.shared.b16 {%0,%1}, [%2];"
                 : "=r"(r0), "=r"(r1) : "r"(addr));
}
__device__ __forceinline__ void mma_bf16(float* d, const uint32_t* a, const uint32_t* b) {
    asm volatile(
        "mma.sync.aligned.m16n8k16.row.col.f32.bf16.bf16.f32 "
        "{%0,%1,%2,%3}, {%4,%5,%6,%7}, {%8,%9}, {%0,%1,%2,%3};"
        : "+f"(d[0]), "+f"(d[1]), "+f"(d[2]), "+f"(d[3])
        : "r"(a[0]), "r"(a[1]), "r"(a[2]), "r"(a[3]), "r"(b[0]), "r"(b[1]));
}
// fast GELU: v * sigmoid(2 * 0.79788456*(v + 0.044715 v^3))
__device__ __forceinline__ float fast_gelu(float v) {
    float t2 = 1.5957691216057308f * v * (1.0f + 0.044715f * v * v);
    return __fdividef(v, 1.0f + __expf(-t2));
}

// ---------------- attention kernel smem layout (bytes) ----------------
#define SA2_OFF   0
#define SB2_OFF   34816
#define SQKV_OFF  69632
#define SAO_OFF   169984
#define SBIAS_OFF 204800
#define SINT_OFF  206736
#define SMEM_ATT  207760
#define QKV_STRIDE_B 784

// ---------------- MLP smem layout ----------------
#define SA_OFF 0
#define SB_OFF 34816
#define SH_OFF 69632
#define SMEM_MLP (SH_OFF + 133120)
#define SA_STRIDE_B 272
#define SB_STRIDE_B 272
#define SH_STRIDE_B 1040

// weight-chunk prefetch helpers: 128x128 bf16 tile, 8 uint4 per thread
__device__ __forceinline__ void pf_load(uint4* pf, const __nv_bfloat16* base,
                                        int stride, int tid) {
    #pragma unroll
    for (int i = 0; i < 8; ++i) {
        int idx = tid + i * 256;
        int r = idx >> 4, c16 = idx & 15;
        pf[i] = __ldg((const uint4*)(base + (size_t)r * stride + c16 * 8));
    }
}
__device__ __forceinline__ void pf_store(const uint4* pf, char* smdst, int tid) {
    #pragma unroll
    for (int i = 0; i < 8; ++i) {
        int idx = tid + i * 256;
        int r = idx >> 4, c16 = idx & 15;
        *(uint4*)(smdst + r * SB_STRIDE_B + c16 * 16) = pf[i];
    }
}

// ================= prep: fp32 -> bf16 weights =================
__global__ void __launch_bounds__(256)
prep_kernel(const float* __restrict__ qkv_w, const float* __restrict__ proj_w,
            const float* __restrict__ w1, const float* __restrict__ w2)
{
    int idx = blockIdx.x * 256 + threadIdx.x;
    if (idx < 49152) {
        g_qkvw[idx] = __float2bfloat16(qkv_w[idx]);
    } else if (idx < 65536) {
        int j = idx - 49152;
        g_projw[j] = __float2bfloat16(proj_w[j]);
    } else if (idx < 131072) {
        int j = idx - 65536;
        g_w1[j] = __float2bfloat16(w1[j]);
    } else {
        int j = idx - 131072;
        g_w2[j] = __float2bfloat16(w2[j]);
    }
}

// ================= attention kernel: fully tensorized =================
__global__ void __launch_bounds__(256)
attn_kernel(const float* __restrict__ inputs, const float* __restrict__ proj_b,
            const float* __restrict__ bias_table,
            const float* __restrict__ g1, const float* __restrict__ b1)
{
    extern __shared__ char smc[];
    const uint32_t sb = smem_u32(smc);
    float* s_bias = (float*)(smc + SBIAS_OFF);
    int*   s_lab  = (int*)(smc + SINT_OFF);
    int*   s_row  = s_lab + 128;

    const int tid  = threadIdx.x;
    const int wid  = tid >> 5;
    const int lane = tid & 31;
    const int wm = wid & 3, wn = wid >> 2;

    // prefetch QKV weight chunk 0 early (overlaps LN)
    uint4 pf[8];
    pf_load(pf, g_qkvw, 384, tid);

    for (int i = tid; i < 484; i += 256) s_bias[i] = bias_table[i];

    // ---------------- Phase A: gather + LN1 -> bf16 A ----------------
    for (int it = 0; it < 16; ++it) {
        int n  = wid + it * 8;
        int gw = blockIdx.x * 2 + (n >> 6);
        int b  = gw >> 9;
        int w9 = gw & 511;
        int G1 = w9 >> 6, G2 = (w9 >> 3) & 7, G3 = w9 & 7;
        int nq = n & 63;
        int t1 = nq >> 4, t2 = (nq >> 2) & 3, t3 = nq & 3;
        int s1 = G1 * 4 + t1, s2 = G2 * 4 + t2, s3 = G3 * 4 + t3;
        int i1 = (s1 + 2) & 31, i2 = (s2 + 2) & 31, i3 = (s3 + 2) & 31;
        int grow = b * 32768 + i1 * 1024 + i2 * 32 + i3;

        float4 v = ((const float4*)(inputs + (size_t)grow * CC))[lane];
        float s  = v.x + v.y + v.z + v.w;
        float ss = v.x*v.x + v.y*v.y + v.z*v.z + v.w*v.w;
        #pragma unroll
        for (int o = 16; o; o >>= 1) {
            s  += __shfl_xor_sync(0xffffffffu, s,  o);
            ss += __shfl_xor_sync(0xffffffffu, ss, o);
        }
        float mean = s * (1.0f / 128.0f);
        float var  = ss * (1.0f / 128.0f) - mean * mean;
        float inv  = rsqrtf(var + 1e-5f);
        float4 gg = ((const float4*)g1)[lane];
        float4 bb = ((const float4*)b1)[lane];
        float o0 = (v.x - mean) * inv * gg.x + bb.x;
        float o1 = (v.y - mean) * inv * gg.y + bb.y;
        float o2 = (v.z - mean) * inv * gg.z + bb.z;
        float o3 = (v.w - mean) * inv * gg.w + bb.w;
        uint32_t p0, p1;
        asm("cvt.rn.bf16x2.f32 %0, %1, %2;" : "=r"(p0) : "f"(o1), "f"(o0));
        asm("cvt.rn.bf16x2.f32 %0, %1, %2;" : "=r"(p1) : "f"(o3), "f"(o2));
        *(uint2*)(smc + SA2_OFF + n * SA_STRIDE_B + lane * 8) = make_uint2(p0, p1);

        if (lane == 0) {
            s_row[n] = grow;
            int r1 = s1 < 28 ? 0 : (s1 < 30 ? 1 : 2);
            int r2 = s2 < 28 ? 0 : (s2 < 30 ? 1 : 2);
            int r3 = s3 < 28 ? 0 : (s3 < 30 ? 1 : 2);
            s_lab[n] = r1 * 9 + r2 * 3 + r3;
        }
    }
    pf_store(pf, smc + SB2_OFF, tid);
    __syncthreads();

    const uint32_t a_row  = (uint32_t)(lane & 15);
    const uint32_t a_koff = (uint32_t)((lane >> 4) * 16);
    const uint32_t b_row  = (uint32_t)(lane & 15);
    const int qr = lane >> 2, qc = (lane & 3) * 2;

    // ---------------- Phase B: QKV GEMM (3 N-chunks of 128), pipelined -----
    for (int chunk = 0; chunk < 3; ++chunk) {
        // prefetch next chunk (or proj weights after the last)
        if (chunk < 2) pf_load(pf, g_qkvw + (chunk + 1) * 128, 384, tid);
        else           pf_load(pf, g_projw, 128, tid);

        float acc[2][8][4];
        #pragma unroll
        for (int i = 0; i < 2; ++i)
            #pragma unroll
            for (int j = 0; j < 8; ++j)
                #pragma unroll
                for (int q = 0; q < 4; ++q) acc[i][j][q] = 0.0f;

        #pragma unroll
        for (int ks = 0; ks < 8; ++ks) {
            uint32_t af[2][4];
            #pragma unroll
            for (int mt = 0; mt < 2; ++mt) {
                uint32_t addr = sb + SA2_OFF
                    + (wm * 32 + mt * 16 + a_row) * SA_STRIDE_B + ks * 32 + a_koff;
                ldsm_x4(addr, af[mt][0], af[mt][1], af[mt][2], af[mt][3]);
            }
            uint32_t bf[8][2];
            #pragma unroll
            for (int nt = 0; nt < 8; ++nt) {
                uint32_t addr = sb + SB2_OFF
                    + (ks * 16 + b_row) * SB_STRIDE_B + (wn * 64 + nt * 8) * 2;
                ldsm_x2_t(addr, bf[nt][0], bf[nt][1]);
            }
            #pragma unroll
            for (int mt = 0; mt < 2; ++mt)
                #pragma unroll
                for (int nt = 0; nt < 8; ++nt)
                    mma_bf16(acc[mt][nt], af[mt], bf[nt]);
        }

        const float scale = (chunk == 0) ? 0.17677669529663687f : 1.0f;
        #pragma unroll
        for (int mt = 0; mt < 2; ++mt)
            #pragma unroll
            for (int nt = 0; nt < 8; ++nt) {
                int col = chunk * 128 + wn * 64 + nt * 8 + qc;
                #pragma unroll
                for (int half = 0; half < 2; ++half) {
                    int r = wm * 32 + mt * 16 + qr + half * 8;
                    float v0 = acc[mt][nt][half * 2 + 0] * scale;
                    float v1 = acc[mt][nt][half * 2 + 1] * scale;
                    uint32_t pk;
                    asm("cvt.rn.bf16x2.f32 %0, %1, %2;" : "=r"(pk) : "f"(v1), "f"(v0));
                    *(uint32_t*)(smc + SQKV_OFF + r * QKV_STRIDE_B + col * 2) = pk;
                }
            }
        __syncthreads();                 // SB2 reads done
        pf_store(pf, smc + SB2_OFF, tid); // next weights in place
        __syncthreads();
    }
    // SB2 now holds proj weights; SQKV complete.

    // ---------------- Phase C: tensorized attention (warp = window x head) --
    {
        const int wloc = wid >> 2;
        const int h    = wid & 3;
        const uint32_t qkvb = sb + SQKV_OFF;
        const uint32_t p_off = (wid < 4) ? (uint32_t)(SA2_OFF + wid * 8192)
                                         : (uint32_t)(SAO_OFF + (wid - 4) * 8192);
        const uint32_t prow = sb + p_off;        // smem-window address (ldmatrix)
        char* const prow_ptr = smc + p_off;      // generic pointer (stores)

        int   labc[16];
        int   offc[16];
        #pragma unroll
        for (int nt = 0; nt < 8; ++nt)
            #pragma unroll
            for (int e = 0; e < 2; ++e) {
                int c = nt * 8 + qc + e;
                labc[nt * 2 + e] = s_lab[wloc * 64 + c];
                offc[nt * 2 + e] = 11 * (c >> 4) + ((c >> 2) & 3) + (c & 3);
            }

        for (int mh = 0; mh < 2; ++mh) {
            float S[2][8][4];
            #pragma unroll
            for (int i = 0; i < 2; ++i)
                #pragma unroll
                for (int j = 0; j < 8; ++j)
                    #pragma unroll
                    for (int q = 0; q < 4; ++q) S[i][j][q] = 0.0f;

            #pragma unroll
            for (int ks = 0; ks < 2; ++ks) {
                uint32_t af[2][4];
                #pragma unroll
                for (int mt = 0; mt < 2; ++mt) {
                    uint32_t addr = qkvb
                        + (wloc * 64 + mh * 32 + mt * 16 + a_row) * QKV_STRIDE_B
                        + h * 64 + ks * 32 + a_koff;
                    ldsm_x4(addr, af[mt][0], af[mt][1], af[mt][2], af[mt][3]);
                }
                uint32_t bf[8][2];
                #pragma unroll
                for (int nt = 0; nt < 8; ++nt) {
                    uint32_t addr = qkvb
                        + (wloc * 64 + nt * 8 + (lane & 7)) * QKV_STRIDE_B
                        + 256 + h * 64 + ks * 32 + ((lane >> 3) & 1) * 16;
                    ldsm_x2(addr, bf[nt][0], bf[nt][1]);
                }
                #pragma unroll
                for (int mt = 0; mt < 2; ++mt)
                    #pragma unroll
                    for (int nt = 0; nt < 8; ++nt)
                        mma_bf16(S[mt][nt], af[mt], bf[nt]);
            }

            #pragma unroll
            for (int mt = 0; mt < 2; ++mt) {
                #pragma unroll
                for (int half = 0; half < 2; ++half) {
                    int nq = mh * 32 + mt * 16 + qr + half * 8;
                    int labn = s_lab[wloc * 64 + nq];
                    int base_n = ((nq >> 4) + 3) * 11 + ((nq >> 2) & 3) + (nq & 3) + 6;

                    float rmax = -1e30f;
                    #pragma unroll
                    for (int nt = 0; nt < 8; ++nt)
                        #pragma unroll
                        for (int e = 0; e < 2; ++e) {
                            float v = S[mt][nt][half * 2 + e]
                                + s_bias[(base_n - offc[nt * 2 + e]) * 4 + h];
                            if (labn != labc[nt * 2 + e]) v -= 100.0f;
                            S[mt][nt][half * 2 + e] = v;
                            rmax = fmaxf(rmax, v);
                        }
                    rmax = fmaxf(rmax, __shfl_xor_sync(0xffffffffu, rmax, 1));
                    rmax = fmaxf(rmax, __shfl_xor_sync(0xffffffffu, rmax, 2));

                    float rsum = 0.0f;
                    #pragma unroll
                    for (int nt = 0; nt < 8; ++nt)
                        #pragma unroll
                        for (int e = 0; e < 2; ++e) {
                            float ev = __expf(S[mt][nt][half * 2 + e] - rmax);
                            S[mt][nt][half * 2 + e] = ev;
                            rsum += ev;
                        }
                    rsum += __shfl_xor_sync(0xffffffffu, rsum, 1);
                    rsum += __shfl_xor_sync(0xffffffffu, rsum, 2);
                    float invs = 1.0f / rsum;

                    int prow_i = nq;
                    #pragma unroll
                    for (int nt = 0; nt < 8; ++nt) {
                        float p0 = S[mt][nt][half * 2 + 0] * invs;
                        float p1 = S[mt][nt][half * 2 + 1] * invs;
                        uint32_t pk;
                        asm("cvt.rn.bf16x2.f32 %0, %1, %2;" : "=r"(pk) : "f"(p1), "f"(p0));
                        int c = nt * 8 + qc;
                        uint32_t byte = prow_i * 128
                            + (uint32_t)(((c >> 3) ^ (prow_i & 7)) * 16) + (c & 7) * 2;
                        *(uint32_t*)(prow_ptr + byte) = pk;
                    }
                }
            }
        }
        __syncwarp();

        float O[4][4][4];
        #pragma unroll
        for (int i = 0; i < 4; ++i)
            #pragma unroll
            for (int j = 0; j < 4; ++j)
                #pragma unroll
                for (int q = 0; q < 4; ++q) O[i][j][q] = 0.0f;

        #pragma unroll
        for (int ks = 0; ks < 4; ++ks) {
            uint32_t af[4][4];
            #pragma unroll
            for (int mt = 0; mt < 4; ++mt) {
                uint32_t r = mt * 16 + a_row;
                uint32_t blk = (uint32_t)((ks * 2 + (lane >> 4)) ^ (r & 7));
                ldsm_x4(prow + r * 128 + blk * 16,
                        af[mt][0], af[mt][1], af[mt][2], af[mt][3]);
            }
            uint32_t bf[4][2];
            #pragma unroll
            for (int nt = 0; nt < 4; ++nt) {
                uint32_t addr = qkvb
                    + (wloc * 64 + ks * 16 + b_row) * QKV_STRIDE_B
                    + 512 + h * 64 + nt * 16;
                ldsm_x2_t(addr, bf[nt][0], bf[nt][1]);
            }
            #pragma unroll
            for (int mt = 0; mt < 4; ++mt)
                #pragma unroll
                for (int nt = 0; nt < 4; ++nt)
                    mma_bf16(O[mt][nt], af[mt], bf[nt]);
        }
        __syncthreads();   // all P reads done before SAO overwritten

        #pragma unroll
        for (int mt = 0; mt < 4; ++mt)
            #pragma unroll
            for (int nt = 0; nt < 4; ++nt) {
                int col = h * 32 + nt * 8 + qc;
                #pragma unroll
                for (int half = 0; half < 2; ++half) {
                    int r = wloc * 64 + mt * 16 + qr + half * 8;
                    uint32_t pk;
                    asm("cvt.rn.bf16x2.f32 %0, %1, %2;" : "=r"(pk)
                        : "f"(O[mt][nt][half * 2 + 1]), "f"(O[mt][nt][half * 2 + 0]));
                    *(uint32_t*)(smc + SAO_OFF + r * SA_STRIDE_B + col * 2) = pk;
                }
            }
    }
    __syncthreads();   // SAO complete; proj weights already in SB2

    // ---------------- Phase D: proj GEMM + residual -> g_x ----------------
    {
        float acc[2][8][4];
        #pragma unroll
        for (int i = 0; i < 2; ++i)
            #pragma unroll
            for (int j = 0; j < 8; ++j)
                #pragma unroll
                for (int q = 0; q < 4; ++q) acc[i][j][q] = 0.0f;

        #pragma unroll
        for (int ks = 0; ks < 8; ++ks) {
            uint32_t af[2][4];
            #pragma unroll
            for (int mt = 0; mt < 2; ++mt) {
                uint32_t addr = sb + SAO_OFF
                    + (wm * 32 + mt * 16 + a_row) * SA_STRIDE_B + ks * 32 + a_koff;
                ldsm_x4(addr, af[mt][0], af[mt][1], af[mt][2], af[mt][3]);
            }
            uint32_t bf[8][2];
            #pragma unroll
            for (int nt = 0; nt < 8; ++nt) {
                uint32_t addr = sb + SB2_OFF
                    + (ks * 16 + b_row) * SB_STRIDE_B + (wn * 64 + nt * 8) * 2;
                ldsm_x2_t(addr, bf[nt][0], bf[nt][1]);
            }
            #pragma unroll
            for (int mt = 0; mt < 2; ++mt)
                #pragma unroll
                for (int nt = 0; nt < 8; ++nt)
                    mma_bf16(acc[mt][nt], af[mt], bf[nt]);
        }

        #pragma unroll
        for (int mt = 0; mt < 2; ++mt)
            #pragma unroll
            for (int nt = 0; nt < 8; ++nt) {
                int col = wn * 64 + nt * 8 + qc;
                float pb0 = __ldg(proj_b + col), pb1 = __ldg(proj_b + col + 1);
                #pragma unroll
                for (int half = 0; half < 2; ++half) {
                    int r = wm * 32 + mt * 16 + qr + half * 8;
                    int grow = s_row[r];
                    float2 xv = *(const float2*)(inputs + (size_t)grow * CC + col);
                    float2 o;
                    o.x = (acc[mt][nt][half * 2 + 0] + pb0) * 0.5f + xv.x;
                    o.y = (acc[mt][nt][half * 2 + 1] + pb1) * 0.5f + xv.y;
                    *(float2*)(g_x + (size_t)grow * CC + col) = o;
                }
            }
    }
}

// ================= MLP via ldmatrix + mma.sync, pipelined ==================
__global__ void __launch_bounds__(256)
mlp_hmma_kernel(const float* __restrict__ g2, const float* __restrict__ b2,
                const float* __restrict__ bb1, const float* __restrict__ bb2,
                float* __restrict__ out)
{
    extern __shared__ char smc[];
    const uint32_t sb = smem_u32(smc);
    const int tid  = threadIdx.x;
    const int wid  = tid >> 5;
    const int lane = tid & 31;
    const size_t row0 = (size_t)blockIdx.x * 128;

    const int wm = wid & 3;
    const int wn = wid >> 2;

    // prefetch w1 chunk 0 early (overlaps LN)
    uint4 pf[8];
    pf_load(pf, g_w1, MLPD, tid);

    for (int it = 0; it < 16; ++it) {
        int r = wid + it * 8;
        float4 v = ((const float4*)(g_x + (row0 + r) * CC))[lane];
        float s  = v.x + v.y + v.z + v.w;
        float ss = v.x*v.x + v.y*v.y + v.z*v.z + v.w*v.w;
        #pragma unroll
        for (int o = 16; o; o >>= 1) {
            s  += __shfl_xor_sync(0xffffffffu, s,  o);
            ss += __shfl_xor_sync(0xffffffffu, ss, o);
        }
        float mean = s * (1.0f / 128.0f);
        float var  = ss * (1.0f / 128.0f) - mean * mean;
        float inv  = rsqrtf(var + 1e-5f);
        float4 gg = ((const float4*)g2)[lane];
        float4 bb = ((const float4*)b2)[lane];
        float o0 = (v.x - mean) * inv * gg.x + bb.x;
        float o1 = (v.y - mean) * inv * gg.y + bb.y;
        float o2 = (v.z - mean) * inv * gg.z + bb.z;
        float o3 = (v.w - mean) * inv * gg.w + bb.w;
        uint32_t p0, p1;
        asm("cvt.rn.bf16x2.f32 %0, %1, %2;" : "=r"(p0) : "f"(o1), "f"(o0));
        asm("cvt.rn.bf16x2.f32 %0, %1, %2;" : "=r"(p1) : "f"(o3), "f"(o2));
        *(uint2*)(smc + SA_OFF + r * SA_STRIDE_B + lane * 8) = make_uint2(p0, p1);
    }
    pf_store(pf, smc + SB_OFF, tid);
    __syncthreads();

    const uint32_t a_row = (uint32_t)(lane & 15);
    const uint32_t a_koff = (uint32_t)((lane >> 4) * 16);
    const uint32_t b_row = (uint32_t)(lane & 15);

    // ---- GEMM1: 4 N-chunks, register-prefetch pipelined ----
    for (int chunk = 0; chunk < 4; ++chunk) {
        if (chunk < 3) pf_load(pf, g_w1 + (chunk + 1) * 128, MLPD, tid);
        else           pf_load(pf, g_w2, CC, tid);   // w2 sub 0

        float acc[2][8][4];
        #pragma unroll
        for (int i = 0; i < 2; ++i)
            #pragma unroll
            for (int j = 0; j < 8; ++j)
                #pragma unroll
                for (int q = 0; q < 4; ++q) acc[i][j][q] = 0.0f;

        #pragma unroll
        for (int ks = 0; ks < 8; ++ks) {
            uint32_t af[2][4];
            #pragma unroll
            for (int mt = 0; mt < 2; ++mt) {
                uint32_t addr = sb + SA_OFF
                    + (wm * 32 + mt * 16 + a_row) * SA_STRIDE_B + ks * 32 + a_koff;
                ldsm_x4(addr, af[mt][0], af[mt][1], af[mt][2], af[mt][3]);
            }
            uint32_t bf[8][2];
            #pragma unroll
            for (int nt = 0; nt < 8; ++nt) {
                uint32_t addr = sb + SB_OFF
                    + (ks * 16 + b_row) * SB_STRIDE_B + (wn * 64 + nt * 8) * 2;
                ldsm_x2_t(addr, bf[nt][0], bf[nt][1]);
            }
            #pragma unroll
            for (int mt = 0; mt < 2; ++mt)
                #pragma unroll
                for (int nt = 0; nt < 8; ++nt)
                    mma_bf16(acc[mt][nt], af[mt], bf[nt]);
        }

        const int qr = lane >> 2, qc = (lane & 3) * 2;
        #pragma unroll
        for (int mt = 0; mt < 2; ++mt) {
            #pragma unroll
            for (int nt = 0; nt < 8; ++nt) {
                int col = chunk * 128 + wn * 64 + nt * 8 + qc;
                float bias0 = __ldg(bb1 + col), bias1 = __ldg(bb1 + col + 1);
                #pragma unroll
                for (int half = 0; half < 2; ++half) {
                    int r = wm * 32 + mt * 16 + qr + half * 8;
                    float v0 = fast_gelu(acc[mt][nt][half * 2 + 0] + bias0);
                    float v1 = fast_gelu(acc[mt][nt][half * 2 + 1] + bias1);
                    uint32_t pk;
                    asm("cvt.rn.bf16x2.f32 %0, %1, %2;" : "=r"(pk) : "f"(v1), "f"(v0));
                    *(uint32_t*)(smc + SH_OFF + r * SH_STRIDE_B + col * 2) = pk;
                }
            }
        }
        __syncthreads();
        pf_store(pf, smc + SB_OFF, tid);
        __syncthreads();
    }

    // ---- GEMM2: K=512 in 4 sub-chunks, pipelined ----
    float acc2[2][8][4];
    #pragma unroll
    for (int i = 0; i < 2; ++i)
        #pragma unroll
        for (int j = 0; j < 8; ++j)
            #pragma unroll
            for (int q = 0; q < 4; ++q) acc2[i][j][q] = 0.0f;

    for (int sub = 0; sub < 4; ++sub) {
        if (sub < 3) pf_load(pf, g_w2 + (size_t)(sub + 1) * 128 * CC, CC, tid);

        #pragma unroll
        for (int ks = 0; ks < 8; ++ks) {
            uint32_t af[2][4];
            #pragma unroll
            for (int mt = 0; mt < 2; ++mt) {
                uint32_t addr = sb + SH_OFF
                    + (wm * 32 + mt * 16 + a_row) * SH_STRIDE_B
                    + (sub * 128 + ks * 16) * 2 + a_koff;
                ldsm_x4(addr, af[mt][0], af[mt][1], af[mt][2], af[mt][3]);
            }
            uint32_t bf[8][2];
            #pragma unroll
            for (int nt = 0; nt < 8; ++nt) {
                uint32_t addr = sb + SB_OFF
                    + (ks * 16 + b_row) * SB_STRIDE_B + (wn * 64 + nt * 8) * 2;
                ldsm_x2_t(addr, bf[nt][0], bf[nt][1]);
            }
            #pragma unroll
            for (int mt = 0; mt < 2; ++mt)
                #pragma unroll
                for (int nt = 0; nt < 8; ++nt)
                    mma_bf16(acc2[mt][nt], af[mt], bf[nt]);
        }
        if (sub < 3) {
            __syncthreads();
            pf_store(pf, smc + SB_OFF, tid);
            __syncthreads();
        }
    }

    {
        const int qr = lane >> 2, qc = (lane & 3) * 2;
        #pragma unroll
        for (int mt = 0; mt < 2; ++mt) {
            #pragma unroll
            for (int nt = 0; nt < 8; ++nt) {
                int col = wn * 64 + nt * 8 + qc;
                float bias0 = __ldg(bb2 + col), bias1 = __ldg(bb2 + col + 1);
                #pragma unroll
                for (int half = 0; half < 2; ++half) {
                    size_t r = row0 + wm * 32 + mt * 16 + qr + half * 8;
                    float2 xv = *(const float2*)(g_x + r * CC + col);
                    float2 o;
                    o.x = (acc2[mt][nt][half * 2 + 0] + bias0) * 0.5f + xv.x;
                    o.y = (acc2[mt][nt][half * 2 + 1] + bias1) * 0.5f + xv.y;
                    *(float2*)(out + r * CC + col) = o;
                }
            }
        }
    }
}

extern "C" void kernel_launch(void* const* d_in, const int* in_sizes, int n_in,
                              void* d_out, int out_size)
{
    const float* inputs     = (const float*)d_in[0];
    const float* qkv_w      = (const float*)d_in[1];
    const float* proj_w     = (const float*)d_in[2];
    const float* proj_b     = (const float*)d_in[3];
    const float* bias_table = (const float*)d_in[4];
    const float* g1         = (const float*)d_in[5];
    const float* b1         = (const float*)d_in[6];
    const float* g2         = (const float*)d_in[7];
    const float* b2         = (const float*)d_in[8];
    const float* w1         = (const float*)d_in[9];
    const float* bb1        = (const float*)d_in[10];
    const float* w2         = (const float*)d_in[11];
    const float* bb2        = (const float*)d_in[12];
    float* out = (float*)d_out;

    cudaFuncSetAttribute(attn_kernel,     cudaFuncAttributeMaxDynamicSharedMemorySize, SMEM_ATT);
    cudaFuncSetAttribute(mlp_hmma_kernel, cudaFuncAttributeMaxDynamicSharedMemorySize, SMEM_MLP);

    prep_kernel<<<768, 256>>>(qkv_w, proj_w, w1, w2);
    attn_kernel<<<RB * 256, 256, SMEM_ATT>>>(inputs, proj_b, bias_table, g1, b1);
    mlp_hmma_kernel<<<TT / 128, 256, SMEM_MLP>>>(g2, b2, bb1, bb2, out);
}